// round 8
// baseline (speedup 1.0000x reference)
#include <cuda_runtime.h>
#include <cuda_fp16.h>
#include <cstdint>

// Problem constants
constexpr int kNB = 2;
constexpr int kNT = 2048;
constexpr int kND = 1024;
constexpr int kNH = 16;
constexpr int kNM = kNB * kNT;   // 4096 rows

// Scratch (allocation-free rule: device globals), all fp16
__device__ __half g_qkv[(size_t)kNM * 3 * kND];   // (4096, 3072)
__device__ __half g_attn[(size_t)kNM * kND];      // (4096, 1024)
__device__ __half g_xh[(size_t)kNM * kND];        // x -> fp16 [m][k]
__device__ __half g_wat[(size_t)3 * kND * kND];   // W_attn^T fp16 [n][k]
__device__ __half g_wpt[(size_t)kND * kND];       // W_proj^T fp16 [n][k]

// ---------------------------------------------------------------------------
// Helpers
// ---------------------------------------------------------------------------
__device__ __forceinline__ uint32_t packh2(float a, float b) {
    __half2 h = __floats2half2_rn(a, b);
    return *(uint32_t*)&h;
}

__device__ __forceinline__ void mma_f16(float4& c, const uint32_t a[4],
                                        const uint32_t b[2]) {
    asm volatile(
        "mma.sync.aligned.m16n8k16.row.col.f32.f16.f16.f32 "
        "{%0,%1,%2,%3}, {%4,%5,%6,%7}, {%8,%9}, {%0,%1,%2,%3};\n"
        : "+f"(c.x), "+f"(c.y), "+f"(c.z), "+f"(c.w)
        : "r"(a[0]), "r"(a[1]), "r"(a[2]), "r"(a[3]), "r"(b[0]), "r"(b[1]));
}

__device__ __forceinline__ void ldsm_x2_trans(uint32_t& r0, uint32_t& r1,
                                              uint32_t saddr) {
    asm volatile("ldmatrix.sync.aligned.m8n8.x2.trans.shared.b16 {%0,%1}, [%2];"
                 : "=r"(r0), "=r"(r1) : "r"(saddr));
}

__device__ __forceinline__ unsigned sptr(const void* p) {
    return (unsigned)__cvta_generic_to_shared(p);
}
#define CP_ASYNC16(dst, src) \
    asm volatile("cp.async.cg.shared.global [%0], [%1], 16;" :: "r"(dst), "l"(src))

// ---------------------------------------------------------------------------
// Prepass: fp32 -> fp16 conversion / transposed conversion
// ---------------------------------------------------------------------------
__global__ void cvt_h(const float* __restrict__ in, __half* __restrict__ out)
{
    int i = blockIdx.x * blockDim.x + threadIdx.x;
    float4 v = ((const float4*)in)[i];
    uint2 o;
    o.x = packh2(v.x, v.y);
    o.y = packh2(v.z, v.w);
    ((uint2*)out)[i] = o;
}

__global__ void transpose_h(const float* __restrict__ in, __half* __restrict__ out,
                            int R, int C)
{
    __shared__ float t[32][33];
    int c0 = blockIdx.x * 32, r0 = blockIdx.y * 32;
    for (int i = threadIdx.y; i < 32; i += 8)
        t[i][threadIdx.x] = in[(size_t)(r0 + i) * C + c0 + threadIdx.x];
    __syncthreads();
    for (int i = threadIdx.y; i < 32; i += 8)
        out[(size_t)(c0 + i) * R + r0 + threadIdx.x] = __float2half(t[threadIdx.x][i]);
}

// ---------------------------------------------------------------------------
// fp16 GEMM: C[M,N] = A[M,K] @ Bt[N,K]^T, A/Bt fp16 k-major.
// 128x128 CTA, BK=32, 256 threads (8 warps 4x2), warp tile 32x64, m16n8k16.
// 3-deep cp.async ring, one __syncthreads per K-iter. 16 warps/SM.
// ---------------------------------------------------------------------------
constexpr int RST  = 20;                 // uints per smem row (32 fp16 + pad)
constexpr int GBUF = 2 * 128 * RST;      // uints per buffer (A+B)
constexpr int GEMM_SMEM = 3 * GBUF * 4;  // 61440 B

template <bool HOUT>
__global__ __launch_bounds__(256, 2) void gemm_f16(
    const __half* __restrict__ A, const __half* __restrict__ Bt,
    void* __restrict__ Cv, int M, int N, int K)
{
    extern __shared__ uint32_t gsh[];

    const int tid  = threadIdx.x;
    const int warp = tid >> 5, lane = tid & 31;
    const int g  = lane >> 2;
    const int i4 = lane & 3;
    const int wm = (warp >> 1) * 32;     // 4 warp-rows of 32
    const int wn = (warp & 1) * 64;      // 2 warp-cols of 64
    const int brow = blockIdx.y * 128;
    const int bcol = blockIdx.x * 128;
    const uint32_t sbase = sptr(gsh);

    float4 acc[2][8];
    #pragma unroll
    for (int mt = 0; mt < 2; mt++)
        #pragma unroll
        for (int nt = 0; nt < 8; nt++)
            acc[mt][nt] = make_float4(0.f, 0.f, 0.f, 0.f);

    const int NIT = K >> 5;

    auto stage = [&](int s, int buf) {
        uint32_t ab = sbase + buf * GBUF * 4;
        uint32_t bb = ab + 128 * RST * 4;
        const __half* Ag = A + (size_t)brow * K + (s << 5);
        const __half* Bg = Bt + (size_t)bcol * K + (s << 5);
        #pragma unroll
        for (int i = 0; i < 2; i++) {
            int id = tid + 256 * i;          // 0..511
            int r = id >> 2, ch = id & 3;    // 128 rows x 4 16B-chunks
            CP_ASYNC16(ab + r * 80 + ch * 16, Ag + (size_t)r * K + ch * 8);
            CP_ASYNC16(bb + r * 80 + ch * 16, Bg + (size_t)r * K + ch * 8);
        }
        asm volatile("cp.async.commit_group;");
    };

    stage(0, 0);
    stage(1, 1);

    #pragma unroll 1
    for (int s = 0; s < NIT; s++) {
        const int b = s % 3;
        if (s < NIT - 1) { asm volatile("cp.async.wait_group 1;"); }
        else             { asm volatile("cp.async.wait_group 0;"); }
        __syncthreads();

        if (s + 2 < NIT) stage(s + 2, (s + 2) % 3);

        const uint32_t* a_src = gsh + b * GBUF;
        const uint32_t* b_src = a_src + 128 * RST;

        #pragma unroll
        for (int kk = 0; kk < 2; kk++) {
            uint32_t af[2][4], bf[8][2];
            #pragma unroll
            for (int mt = 0; mt < 2; mt++) {
                int row = wm + mt * 16 + g;
                af[mt][0] = a_src[row * RST + kk * 8 + i4];
                af[mt][1] = a_src[(row + 8) * RST + kk * 8 + i4];
                af[mt][2] = a_src[row * RST + kk * 8 + i4 + 4];
                af[mt][3] = a_src[(row + 8) * RST + kk * 8 + i4 + 4];
            }
            #pragma unroll
            for (int nt = 0; nt < 8; nt++) {
                int cc = wn + nt * 8 + g;
                bf[nt][0] = b_src[cc * RST + kk * 8 + i4];
                bf[nt][1] = b_src[cc * RST + kk * 8 + i4 + 4];
            }
            #pragma unroll
            for (int mt = 0; mt < 2; mt++)
                #pragma unroll
                for (int nt = 0; nt < 8; nt++)
                    mma_f16(acc[mt][nt], af[mt], bf[nt]);
        }
    }

    // Epilogue
    #pragma unroll
    for (int mt = 0; mt < 2; mt++) {
        int row = brow + wm + mt * 16 + g;
        #pragma unroll
        for (int nt = 0; nt < 8; nt++) {
            int col = bcol + wn + nt * 8 + i4 * 2;
            if (HOUT) {
                __half* C = (__half*)Cv;
                *(uint32_t*)&C[(size_t)row * N + col] =
                    packh2(acc[mt][nt].x, acc[mt][nt].y);
                *(uint32_t*)&C[(size_t)(row + 8) * N + col] =
                    packh2(acc[mt][nt].z, acc[mt][nt].w);
            } else {
                float* C = (float*)Cv;
                *(float2*)&C[(size_t)row * N + col] =
                    make_float2(acc[mt][nt].x, acc[mt][nt].y);
                *(float2*)&C[(size_t)(row + 8) * N + col] =
                    make_float2(acc[mt][nt].z, acc[mt][nt].w);
            }
        }
    }
}

// ---------------------------------------------------------------------------
// Flash attention, fp16 MMA (m16n8k16), RoPE fused. BM=128 (8 warps x m16),
// BN=64, HD=64, causal, 256 threads. qkv fp16 in, attn fp16 out.
// ---------------------------------------------------------------------------
constexpr int QST = 36;   // uints per row (32 data + 4 pad)
constexpr int KST = 36;
constexpr int VST = 36;
constexpr int PST = 36;
constexpr int ATTN_SMEM = (128 * QST + 64 * KST + 64 * VST + 128 * PST) * 4; // 55296

__global__ __launch_bounds__(256, 2) void attn_f16(
    const __half* __restrict__ qkv, const float* __restrict__ rope,
    __half* __restrict__ out)
{
    extern __shared__ uint32_t ash[];
    uint32_t* Qs = ash;                  // [128 m][QST] fp16 pairs (roped, scaled)
    uint32_t* Ks = Qs + 128 * QST;       // [64 key][KST] (roped)
    uint32_t* Vs = Ks + 64 * KST;        // [64 key][VST] natural
    uint32_t* Ps = Vs + 64 * VST;        // [128 m][PST] P fp16 (warp-private rows)

    const int tid  = threadIdx.x;
    const int warp = tid >> 5, lane = tid & 31;
    const int g  = lane >> 2;
    const int i4 = lane & 3;
    const int qt = gridDim.x - 1 - blockIdx.x;   // big tiles first
    const int h  = blockIdx.y;
    const int b  = blockIdx.z;
    const uint32_t vbase = sptr(Vs);

    // ---- Load Q tile (128 rows x 64 dims), RoPE + scale ----
    #pragma unroll
    for (int i = 0; i < 8; i++) {
        int id  = tid + 256 * i;          // 0..2047
        int row = id & 127;
        int d4  = (id >> 7) * 4;
        int t   = qt * 128 + row;
        uint2 raw = *(const uint2*)
            &qkv[((size_t)(b * kNT + t)) * 3072 + h * 64 + d4];
        __half2 p01 = *(__half2*)&raw.x, p23 = *(__half2*)&raw.y;
        float vx = __low2float(p01), vy = __high2float(p01);
        float vz = __low2float(p23), vw = __high2float(p23);
        int p0 = d4 >> 1;
        float c0 = rope[(t * 32 + p0) * 2],     s0 = rope[(t * 32 + p0) * 2 + 1];
        float c1 = rope[(t * 32 + p0 + 1) * 2], s1 = rope[(t * 32 + p0 + 1) * 2 + 1];
        float q0 = (vx * c0 - vy * s0) * 0.125f, q1 = (vy * c0 + vx * s0) * 0.125f;
        float q2 = (vz * c1 - vw * s1) * 0.125f, q3 = (vw * c1 + vz * s1) * 0.125f;
        uint2 st = make_uint2(packh2(q0, q1), packh2(q2, q3));
        *(uint2*)&Qs[row * QST + (d4 >> 1)] = st;
    }
    __syncthreads();

    // ---- Hoist Q A-fragments (invariant across kt); warp owns rows w*16.. ----
    uint32_t qf[4][4];
    {
        int r = warp * 16 + g;
        #pragma unroll
        for (int kk = 0; kk < 4; kk++) {
            qf[kk][0] = Qs[r * QST + kk * 8 + i4];
            qf[kk][1] = Qs[(r + 8) * QST + kk * 8 + i4];
            qf[kk][2] = Qs[r * QST + kk * 8 + i4 + 4];
            qf[kk][3] = Qs[(r + 8) * QST + kk * 8 + i4 + 4];
        }
    }

    float m0 = -1e30f, m1 = -1e30f, l0 = 0.f, l1 = 0.f;
    float4 o[8];
    #pragma unroll
    for (int nt = 0; nt < 8; nt++) o[nt] = make_float4(0.f, 0.f, 0.f, 0.f);

    const int nkt = 2 * qt + 2;
    for (int kt = 0; kt < nkt; kt++) {
        __syncthreads();   // previous PV reads of Ks/Vs done
        // ---- Load K (roped) and V tiles ----
        #pragma unroll
        for (int i = 0; i < 4; i++) {
            int id  = tid + 256 * i;      // 0..1023
            int row = id >> 4;
            int d4  = (id & 15) * 4;
            int t   = kt * 64 + row;
            size_t gb = ((size_t)(b * kNT + t)) * 3072 + h * 64 + d4;
            uint2 kraw = *(const uint2*)&qkv[gb + 1024];
            __half2 k01 = *(__half2*)&kraw.x, k23 = *(__half2*)&kraw.y;
            float kx = __low2float(k01), ky = __high2float(k01);
            float kz = __low2float(k23), kw = __high2float(k23);
            int p0 = d4 >> 1;
            float c0 = rope[(t * 32 + p0) * 2],     s0 = rope[(t * 32 + p0) * 2 + 1];
            float c1 = rope[(t * 32 + p0 + 1) * 2], s1 = rope[(t * 32 + p0 + 1) * 2 + 1];
            uint2 kst = make_uint2(packh2(kx * c0 - ky * s0, ky * c0 + kx * s0),
                                   packh2(kz * c1 - kw * s1, kw * c1 + kz * s1));
            *(uint2*)&Ks[row * KST + (d4 >> 1)] = kst;
            uint2 vraw = *(const uint2*)&qkv[gb + 2048];
            *(uint2*)&Vs[row * VST + (d4 >> 1)] = vraw;
        }
        __syncthreads();

        // Warps whose rows are entirely left of this key tile skip compute.
        if (kt * 64 <= qt * 128 + warp * 16 + 15) {
            // ---- S = Q @ K^T ----
            float4 s[8];
            #pragma unroll
            for (int nt = 0; nt < 8; nt++) s[nt] = make_float4(0.f, 0.f, 0.f, 0.f);

            #pragma unroll
            for (int kk = 0; kk < 4; kk++) {
                #pragma unroll
                for (int nt = 0; nt < 8; nt++) {
                    uint32_t bf[2];
                    int key = nt * 8 + g;
                    bf[0] = Ks[key * KST + kk * 8 + i4];
                    bf[1] = Ks[key * KST + kk * 8 + i4 + 4];
                    mma_f16(s[nt], qf[kk], bf);
                }
            }

            // ---- Causal mask ----
            if (kt >= 2 * qt) {
                int r0 = qt * 128 + warp * 16 + g;
                #pragma unroll
                for (int nt = 0; nt < 8; nt++) {
                    int c0 = kt * 64 + nt * 8 + i4 * 2;
                    if (c0     > r0)     s[nt].x = -1e30f;
                    if (c0 + 1 > r0)     s[nt].y = -1e30f;
                    if (c0     > r0 + 8) s[nt].z = -1e30f;
                    if (c0 + 1 > r0 + 8) s[nt].w = -1e30f;
                }
            }

            // ---- Online softmax + P store (fp16, warp-private rows) ----
            {
                float mx0 = -1e30f, mx1 = -1e30f;
                #pragma unroll
                for (int nt = 0; nt < 8; nt++) {
                    mx0 = fmaxf(mx0, fmaxf(s[nt].x, s[nt].y));
                    mx1 = fmaxf(mx1, fmaxf(s[nt].z, s[nt].w));
                }
                mx0 = fmaxf(mx0, __shfl_xor_sync(0xffffffffu, mx0, 1));
                mx0 = fmaxf(mx0, __shfl_xor_sync(0xffffffffu, mx0, 2));
                mx1 = fmaxf(mx1, __shfl_xor_sync(0xffffffffu, mx1, 1));
                mx1 = fmaxf(mx1, __shfl_xor_sync(0xffffffffu, mx1, 2));
                float nm0 = fmaxf(m0, mx0), nm1 = fmaxf(m1, mx1);
                float f0 = __expf(m0 - nm0), f1 = __expf(m1 - nm1);
                float sum0 = 0.f, sum1 = 0.f;
                int r = warp * 16 + g;
                #pragma unroll
                for (int nt = 0; nt < 8; nt++) {
                    float px = __expf(s[nt].x - nm0);
                    float py = __expf(s[nt].y - nm0);
                    float pz = __expf(s[nt].z - nm1);
                    float pw = __expf(s[nt].w - nm1);
                    sum0 += px + py;
                    sum1 += pz + pw;
                    Ps[r * PST + nt * 4 + i4]       = packh2(px, py);
                    Ps[(r + 8) * PST + nt * 4 + i4] = packh2(pz, pw);
                }
                sum0 += __shfl_xor_sync(0xffffffffu, sum0, 1);
                sum0 += __shfl_xor_sync(0xffffffffu, sum0, 2);
                sum1 += __shfl_xor_sync(0xffffffffu, sum1, 1);
                sum1 += __shfl_xor_sync(0xffffffffu, sum1, 2);
                l0 = l0 * f0 + sum0;  m0 = nm0;
                l1 = l1 * f1 + sum1;  m1 = nm1;
                #pragma unroll
                for (int nt = 0; nt < 8; nt++) {
                    o[nt].x *= f0; o[nt].y *= f0;
                    o[nt].z *= f1; o[nt].w *= f1;
                }
            }
            __syncwarp();   // Ps rows are warp-private

            // ---- O += P @ V (V fragments via ldmatrix.trans) ----
            #pragma unroll
            for (int kk = 0; kk < 4; kk++) {
                uint32_t af[4];
                int r = warp * 16 + g;
                af[0] = Ps[r * PST + kk * 8 + i4];
                af[1] = Ps[(r + 8) * PST + kk * 8 + i4];
                af[2] = Ps[r * PST + kk * 8 + i4 + 4];
                af[3] = Ps[(r + 8) * PST + kk * 8 + i4 + 4];
                #pragma unroll
                for (int nt = 0; nt < 8; nt++) {
                    uint32_t bf[2];
                    uint32_t va = vbase +
                        ((kk * 16 + (lane & 15)) * VST + nt * 4) * 4;
                    ldsm_x2_trans(bf[0], bf[1], va);
                    mma_f16(o[nt], af, bf);
                }
            }
        }
    }

    // ---- Epilogue: fp16 output ----
    {
        float inv0 = 1.0f / l0, inv1 = 1.0f / l1;
        int r = qt * 128 + warp * 16 + g;
        #pragma unroll
        for (int nt = 0; nt < 8; nt++) {
            int col = h * 64 + nt * 8 + i4 * 2;
            *(uint32_t*)&out[((size_t)(b * kNT + r)) * 1024 + col] =
                packh2(o[nt].x * inv0, o[nt].y * inv0);
            *(uint32_t*)&out[((size_t)(b * kNT + r + 8)) * 1024 + col] =
                packh2(o[nt].z * inv1, o[nt].w * inv1);
        }
    }
}

// ---------------------------------------------------------------------------
// Launch
// ---------------------------------------------------------------------------
extern "C" void kernel_launch(void* const* d_in, const int* in_sizes, int n_in,
                              void* d_out, int out_size)
{
    const float* x      = (const float*)d_in[0];
    const float* rope   = (const float*)d_in[1];
    const float* W_attn = (const float*)d_in[2];
    const float* W_proj = (const float*)d_in[3];
    float* out = (float*)d_out;

    __half* qkv;  cudaGetSymbolAddress((void**)&qkv,  g_qkv);
    __half* attn; cudaGetSymbolAddress((void**)&attn, g_attn);
    __half* xh;   cudaGetSymbolAddress((void**)&xh,   g_xh);
    __half* wat;  cudaGetSymbolAddress((void**)&wat,  g_wat);
    __half* wpt;  cudaGetSymbolAddress((void**)&wpt,  g_wpt);

    cudaFuncSetAttribute(gemm_f16<true>,
                         cudaFuncAttributeMaxDynamicSharedMemorySize, GEMM_SMEM);
    cudaFuncSetAttribute(gemm_f16<false>,
                         cudaFuncAttributeMaxDynamicSharedMemorySize, GEMM_SMEM);
    cudaFuncSetAttribute(attn_f16,
                         cudaFuncAttributeMaxDynamicSharedMemorySize, ATTN_SMEM);

    // Prepass: x -> fp16; W_attn/W_proj -> fp16 transposed [n][k]
    cvt_h<<<(kNM * kND / 4) / 256, 256>>>(x, xh);
    transpose_h<<<dim3(3 * kND / 32, kND / 32), dim3(32, 8)>>>(W_attn, wat,
                                                               kND, 3 * kND);
    transpose_h<<<dim3(kND / 32, kND / 32), dim3(32, 8)>>>(W_proj, wpt,
                                                           kND, kND);

    // 1. QKV = x @ W_attn : fp16 out
    gemm_f16<true><<<dim3(3 * kND / 128, kNM / 128), 256, GEMM_SMEM>>>(
        xh, wat, qkv, kNM, 3 * kND, kND);

    // 2. Causal flash attention (RoPE fused), fp16 in/out
    attn_f16<<<dim3(kNT / 128, kNH, kNB), 256, ATTN_SMEM>>>(qkv, rope, attn);

    // 3. out = attn @ W_proj : fp32 out
    gemm_f16<false><<<dim3(kND / 128, kNM / 128), 256, GEMM_SMEM>>>(
        attn, wpt, out, kNM, kND, kND);
}

// round 9
// speedup vs baseline: 1.1650x; 1.1650x over previous
#include <cuda_runtime.h>
#include <cuda_fp16.h>
#include <cstdint>

// Problem constants
constexpr int kNB = 2;
constexpr int kNT = 2048;
constexpr int kND = 1024;
constexpr int kNH = 16;
constexpr int kNM = kNB * kNT;   // 4096 rows

// Scratch (allocation-free rule: device globals), all fp16
__device__ __half g_qkv[(size_t)kNM * 3 * kND];   // (4096, 3072)
__device__ __half g_attn[(size_t)kNM * kND];      // (4096, 1024)
__device__ __half g_xh[(size_t)kNM * kND];        // x -> fp16 [m][k]
__device__ __half g_wat[(size_t)3 * kND * kND];   // W_attn^T fp16 [n][k]
__device__ __half g_wpt[(size_t)kND * kND];       // W_proj^T fp16 [n][k]

// ---------------------------------------------------------------------------
// Helpers
// ---------------------------------------------------------------------------
__device__ __forceinline__ uint32_t packh2(float a, float b) {
    __half2 h = __floats2half2_rn(a, b);
    return *(uint32_t*)&h;
}

__device__ __forceinline__ void mma_f16(float4& c, const uint32_t a[4],
                                        const uint32_t b[2]) {
    asm volatile(
        "mma.sync.aligned.m16n8k16.row.col.f32.f16.f16.f32 "
        "{%0,%1,%2,%3}, {%4,%5,%6,%7}, {%8,%9}, {%0,%1,%2,%3};\n"
        : "+f"(c.x), "+f"(c.y), "+f"(c.z), "+f"(c.w)
        : "r"(a[0]), "r"(a[1]), "r"(a[2]), "r"(a[3]), "r"(b[0]), "r"(b[1]));
}

#define LDSM_X4(r0, r1, r2, r3, addr) \
    asm volatile("ldmatrix.sync.aligned.m8n8.x4.shared.b16 {%0,%1,%2,%3}, [%4];" \
                 : "=r"(r0), "=r"(r1), "=r"(r2), "=r"(r3) : "r"(addr))

__device__ __forceinline__ void ldsm_x2_trans(uint32_t& r0, uint32_t& r1,
                                              uint32_t saddr) {
    asm volatile("ldmatrix.sync.aligned.m8n8.x2.trans.shared.b16 {%0,%1}, [%2];"
                 : "=r"(r0), "=r"(r1) : "r"(saddr));
}

__device__ __forceinline__ unsigned sptr(const void* p) {
    return (unsigned)__cvta_generic_to_shared(p);
}
#define CP_ASYNC16(dst, src) \
    asm volatile("cp.async.cg.shared.global [%0], [%1], 16;" :: "r"(dst), "l"(src))

// ---------------------------------------------------------------------------
// Prepass: fp32 -> fp16 conversion / transposed conversion
// ---------------------------------------------------------------------------
__global__ void cvt_h(const float* __restrict__ in, __half* __restrict__ out)
{
    int i = blockIdx.x * blockDim.x + threadIdx.x;
    float4 v = ((const float4*)in)[i];
    uint2 o;
    o.x = packh2(v.x, v.y);
    o.y = packh2(v.z, v.w);
    ((uint2*)out)[i] = o;
}

__global__ void transpose_h(const float* __restrict__ in, __half* __restrict__ out,
                            int R, int C)
{
    __shared__ float t[32][33];
    int c0 = blockIdx.x * 32, r0 = blockIdx.y * 32;
    for (int i = threadIdx.y; i < 32; i += 8)
        t[i][threadIdx.x] = in[(size_t)(r0 + i) * C + c0 + threadIdx.x];
    __syncthreads();
    for (int i = threadIdx.y; i < 32; i += 8)
        out[(size_t)(c0 + i) * R + r0 + threadIdx.x] = __float2half(t[threadIdx.x][i]);
}

// ---------------------------------------------------------------------------
// fp16 GEMM: C[M,N] = A[M,K] @ Bt[N,K]^T, A/Bt fp16 k-major.
// 128x128 CTA, BK=32, 128 threads (4 warps 2x2), warp tile 64x64, m16n8k16.
// ldmatrix.x4 fragment loads; 3-deep cp.async ring; one sync per K-iter.
// ---------------------------------------------------------------------------
constexpr int RST  = 20;                 // uints per smem row (32 fp16 + pad)
constexpr int GBUF = 2 * 128 * RST;      // uints per buffer (A+B)
constexpr int GEMM_SMEM = 3 * GBUF * 4;  // 61440 B

template <bool HOUT>
__global__ __launch_bounds__(128, 2) void gemm_f16(
    const __half* __restrict__ A, const __half* __restrict__ Bt,
    void* __restrict__ Cv, int M, int N, int K)
{
    extern __shared__ uint32_t gsh[];

    const int tid  = threadIdx.x;
    const int warp = tid >> 5, lane = tid & 31;
    const int g  = lane >> 2;
    const int i4 = lane & 3;
    const int wm = (warp >> 1) * 64;
    const int wn = (warp & 1) * 64;
    const int brow = blockIdx.y * 128;
    const int bcol = blockIdx.x * 128;
    const uint32_t sbase = sptr(gsh);

    // ldmatrix address components (bytes)
    const int a_row = lane & 15;                 // + wm + mt*16
    const int a_col = (lane >> 4) * 16;          // byte offset of k8-group
    const int b_row = (lane & 7) + ((lane >> 4) & 1) * 8;   // + wn + ntp*16
    const int b_col = ((lane >> 3) & 1) * 16;    // byte offset

    float4 acc[4][8];
    #pragma unroll
    for (int mt = 0; mt < 4; mt++)
        #pragma unroll
        for (int nt = 0; nt < 8; nt++)
            acc[mt][nt] = make_float4(0.f, 0.f, 0.f, 0.f);

    const int NIT = K >> 5;

    auto stage = [&](int s, int buf) {
        uint32_t ab = sbase + buf * GBUF * 4;
        uint32_t bb = ab + 128 * RST * 4;
        const __half* Ag = A + (size_t)brow * K + (s << 5);
        const __half* Bg = Bt + (size_t)bcol * K + (s << 5);
        #pragma unroll
        for (int i = 0; i < 4; i++) {
            int id = tid + 128 * i;          // 0..511
            int r = id >> 2, ch = id & 3;    // 128 rows x 4 16B-chunks
            CP_ASYNC16(ab + r * 80 + ch * 16, Ag + (size_t)r * K + ch * 8);
            CP_ASYNC16(bb + r * 80 + ch * 16, Bg + (size_t)r * K + ch * 8);
        }
        asm volatile("cp.async.commit_group;");
    };

    stage(0, 0);
    stage(1, 1);

    #pragma unroll 1
    for (int s = 0; s < NIT; s++) {
        const int b = s % 3;
        if (s < NIT - 1) { asm volatile("cp.async.wait_group 1;"); }
        else             { asm volatile("cp.async.wait_group 0;"); }
        __syncthreads();

        if (s + 2 < NIT) stage(s + 2, (s + 2) % 3);

        const uint32_t a_s = sbase + b * GBUF * 4;
        const uint32_t b_s = a_s + 128 * RST * 4;

        #pragma unroll
        for (int kk = 0; kk < 2; kk++) {
            uint32_t af[4][4], bf[8][2];
            #pragma unroll
            for (int mt = 0; mt < 4; mt++) {
                uint32_t ad = a_s + (wm + mt * 16 + a_row) * 80
                                  + kk * 32 + a_col;
                LDSM_X4(af[mt][0], af[mt][1], af[mt][2], af[mt][3], ad);
            }
            #pragma unroll
            for (int ntp = 0; ntp < 4; ntp++) {
                uint32_t bd = b_s + (wn + ntp * 16 + b_row) * 80
                                  + kk * 32 + b_col;
                LDSM_X4(bf[2 * ntp][0], bf[2 * ntp][1],
                        bf[2 * ntp + 1][0], bf[2 * ntp + 1][1], bd);
            }
            #pragma unroll
            for (int mt = 0; mt < 4; mt++)
                #pragma unroll
                for (int nt = 0; nt < 8; nt++)
                    mma_f16(acc[mt][nt], af[mt], bf[nt]);
        }
    }

    // Epilogue
    #pragma unroll
    for (int mt = 0; mt < 4; mt++) {
        int row = brow + wm + mt * 16 + g;
        #pragma unroll
        for (int nt = 0; nt < 8; nt++) {
            int col = bcol + wn + nt * 8 + i4 * 2;
            if (HOUT) {
                __half* C = (__half*)Cv;
                *(uint32_t*)&C[(size_t)row * N + col] =
                    packh2(acc[mt][nt].x, acc[mt][nt].y);
                *(uint32_t*)&C[(size_t)(row + 8) * N + col] =
                    packh2(acc[mt][nt].z, acc[mt][nt].w);
            } else {
                float* C = (float*)Cv;
                *(float2*)&C[(size_t)row * N + col] =
                    make_float2(acc[mt][nt].x, acc[mt][nt].y);
                *(float2*)&C[(size_t)(row + 8) * N + col] =
                    make_float2(acc[mt][nt].z, acc[mt][nt].w);
            }
        }
    }
}

// ---------------------------------------------------------------------------
// Flash attention, fp16 MMA (m16n8k16), RoPE fused. BM=128 (4 warps x m32),
// BN=64, HD=64, causal, 128 threads. ldmatrix fragment loads.
// ---------------------------------------------------------------------------
constexpr int QST = 36;   // uints per row (32 data + 4 pad)
constexpr int KST = 36;
constexpr int VST = 36;
constexpr int PST = 36;
constexpr int ATTN_SMEM = (128 * QST + 64 * KST + 64 * VST + 128 * PST) * 4; // 55296

__global__ __launch_bounds__(128, 2) void attn_f16(
    const __half* __restrict__ qkv, const float* __restrict__ rope,
    __half* __restrict__ out)
{
    extern __shared__ uint32_t ash[];
    uint32_t* Qs = ash;                  // [128 m][QST] fp16 pairs (roped, scaled)
    uint32_t* Ks = Qs + 128 * QST;       // [64 key][KST] (roped)
    uint32_t* Vs = Ks + 64 * KST;        // [64 key][VST] natural
    uint32_t* Ps = Vs + 64 * VST;        // [128 m][PST] P fp16 (warp-private rows)

    const int tid  = threadIdx.x;
    const int warp = tid >> 5, lane = tid & 31;
    const int g  = lane >> 2;
    const int i4 = lane & 3;
    const int qt = gridDim.x - 1 - blockIdx.x;   // big tiles first
    const int h  = blockIdx.y;
    const int b  = blockIdx.z;
    const uint32_t kbase = sptr(Ks);
    const uint32_t vbase = sptr(Vs);
    const uint32_t pbase = sptr(Ps);

    // ldmatrix address components
    const int a_row = lane & 15;
    const int a_col = (lane >> 4) * 16;
    const int b_row = (lane & 7) + ((lane >> 4) & 1) * 8;
    const int b_col = ((lane >> 3) & 1) * 16;

    // ---- Load Q tile (128 rows x 64 dims), RoPE + scale ----
    #pragma unroll
    for (int i = 0; i < 16; i++) {
        int id  = tid + 128 * i;          // 0..2047
        int row = id & 127;
        int d4  = (id >> 7) * 4;
        int t   = qt * 128 + row;
        uint2 raw = *(const uint2*)
            &qkv[((size_t)(b * kNT + t)) * 3072 + h * 64 + d4];
        __half2 p01 = *(__half2*)&raw.x, p23 = *(__half2*)&raw.y;
        float vx = __low2float(p01), vy = __high2float(p01);
        float vz = __low2float(p23), vw = __high2float(p23);
        int p0 = d4 >> 1;
        float c0 = rope[(t * 32 + p0) * 2],     s0 = rope[(t * 32 + p0) * 2 + 1];
        float c1 = rope[(t * 32 + p0 + 1) * 2], s1 = rope[(t * 32 + p0 + 1) * 2 + 1];
        float q0 = (vx * c0 - vy * s0) * 0.125f, q1 = (vy * c0 + vx * s0) * 0.125f;
        float q2 = (vz * c1 - vw * s1) * 0.125f, q3 = (vw * c1 + vz * s1) * 0.125f;
        uint2 st = make_uint2(packh2(q0, q1), packh2(q2, q3));
        *(uint2*)&Qs[row * QST + (d4 >> 1)] = st;
    }
    __syncthreads();

    // ---- Hoist Q A-fragments (invariant across kt) ----
    uint32_t qf[2][4][4];
    #pragma unroll
    for (int mt = 0; mt < 2; mt++) {
        uint32_t qb = sptr(Qs);
        #pragma unroll
        for (int kk = 0; kk < 4; kk++) {
            uint32_t ad = qb + (warp * 32 + mt * 16 + a_row) * 144
                             + kk * 32 + a_col;
            LDSM_X4(qf[mt][kk][0], qf[mt][kk][1], qf[mt][kk][2], qf[mt][kk][3], ad);
        }
    }

    float m[2][2], l[2][2];
    #pragma unroll
    for (int mt = 0; mt < 2; mt++) {
        m[mt][0] = m[mt][1] = -1e30f;
        l[mt][0] = l[mt][1] = 0.f;
    }
    float4 o[2][8];
    #pragma unroll
    for (int mt = 0; mt < 2; mt++)
        #pragma unroll
        for (int nt = 0; nt < 8; nt++)
            o[mt][nt] = make_float4(0.f, 0.f, 0.f, 0.f);

    const int nkt = 2 * qt + 2;
    for (int kt = 0; kt < nkt; kt++) {
        __syncthreads();   // previous PV reads of Ks/Vs done
        // ---- Load K (roped) and V tiles ----
        #pragma unroll
        for (int i = 0; i < 8; i++) {
            int id  = tid + 128 * i;      // 0..1023
            int row = id >> 4;
            int d4  = (id & 15) * 4;
            int t   = kt * 64 + row;
            size_t gb = ((size_t)(b * kNT + t)) * 3072 + h * 64 + d4;
            uint2 kraw = *(const uint2*)&qkv[gb + 1024];
            __half2 k01 = *(__half2*)&kraw.x, k23 = *(__half2*)&kraw.y;
            float kx = __low2float(k01), ky = __high2float(k01);
            float kz = __low2float(k23), kw = __high2float(k23);
            int p0 = d4 >> 1;
            float c0 = rope[(t * 32 + p0) * 2],     s0 = rope[(t * 32 + p0) * 2 + 1];
            float c1 = rope[(t * 32 + p0 + 1) * 2], s1 = rope[(t * 32 + p0 + 1) * 2 + 1];
            uint2 kst = make_uint2(packh2(kx * c0 - ky * s0, ky * c0 + kx * s0),
                                   packh2(kz * c1 - kw * s1, kw * c1 + kz * s1));
            *(uint2*)&Ks[row * KST + (d4 >> 1)] = kst;
            uint2 vraw = *(const uint2*)&qkv[gb + 2048];
            *(uint2*)&Vs[row * VST + (d4 >> 1)] = vraw;
        }
        __syncthreads();

        // Warps whose rows are entirely left of this key tile skip compute.
        if (kt * 64 <= qt * 128 + warp * 32 + 31) {
            // ---- S = Q @ K^T ----
            float4 s[2][8];
            #pragma unroll
            for (int mt = 0; mt < 2; mt++)
                #pragma unroll
                for (int nt = 0; nt < 8; nt++)
                    s[mt][nt] = make_float4(0.f, 0.f, 0.f, 0.f);

            #pragma unroll
            for (int kk = 0; kk < 4; kk++) {
                uint32_t bf[8][2];
                #pragma unroll
                for (int ntp = 0; ntp < 4; ntp++) {
                    uint32_t bd = kbase + (ntp * 16 + b_row) * 144
                                        + kk * 32 + b_col;
                    LDSM_X4(bf[2 * ntp][0], bf[2 * ntp][1],
                            bf[2 * ntp + 1][0], bf[2 * ntp + 1][1], bd);
                }
                #pragma unroll
                for (int nt = 0; nt < 8; nt++) {
                    mma_f16(s[0][nt], qf[0][kk], bf[nt]);
                    mma_f16(s[1][nt], qf[1][kk], bf[nt]);
                }
            }

            // ---- Causal mask ----
            if (kt >= 2 * qt) {
                #pragma unroll
                for (int mt = 0; mt < 2; mt++) {
                    int r0 = qt * 128 + warp * 32 + mt * 16 + g;
                    #pragma unroll
                    for (int nt = 0; nt < 8; nt++) {
                        int c0 = kt * 64 + nt * 8 + i4 * 2;
                        if (c0     > r0)     s[mt][nt].x = -1e30f;
                        if (c0 + 1 > r0)     s[mt][nt].y = -1e30f;
                        if (c0     > r0 + 8) s[mt][nt].z = -1e30f;
                        if (c0 + 1 > r0 + 8) s[mt][nt].w = -1e30f;
                    }
                }
            }

            // ---- Online softmax + P store (fp16, warp-private rows) ----
            #pragma unroll
            for (int mt = 0; mt < 2; mt++) {
                float mx0 = -1e30f, mx1 = -1e30f;
                #pragma unroll
                for (int nt = 0; nt < 8; nt++) {
                    mx0 = fmaxf(mx0, fmaxf(s[mt][nt].x, s[mt][nt].y));
                    mx1 = fmaxf(mx1, fmaxf(s[mt][nt].z, s[mt][nt].w));
                }
                mx0 = fmaxf(mx0, __shfl_xor_sync(0xffffffffu, mx0, 1));
                mx0 = fmaxf(mx0, __shfl_xor_sync(0xffffffffu, mx0, 2));
                mx1 = fmaxf(mx1, __shfl_xor_sync(0xffffffffu, mx1, 1));
                mx1 = fmaxf(mx1, __shfl_xor_sync(0xffffffffu, mx1, 2));
                float nm0 = fmaxf(m[mt][0], mx0), nm1 = fmaxf(m[mt][1], mx1);
                float f0 = __expf(m[mt][0] - nm0), f1 = __expf(m[mt][1] - nm1);
                float sum0 = 0.f, sum1 = 0.f;
                int r = warp * 32 + mt * 16 + g;
                #pragma unroll
                for (int nt = 0; nt < 8; nt++) {
                    float px = __expf(s[mt][nt].x - nm0);
                    float py = __expf(s[mt][nt].y - nm0);
                    float pz = __expf(s[mt][nt].z - nm1);
                    float pw = __expf(s[mt][nt].w - nm1);
                    sum0 += px + py;
                    sum1 += pz + pw;
                    Ps[r * PST + nt * 4 + i4]       = packh2(px, py);
                    Ps[(r + 8) * PST + nt * 4 + i4] = packh2(pz, pw);
                }
                sum0 += __shfl_xor_sync(0xffffffffu, sum0, 1);
                sum0 += __shfl_xor_sync(0xffffffffu, sum0, 2);
                sum1 += __shfl_xor_sync(0xffffffffu, sum1, 1);
                sum1 += __shfl_xor_sync(0xffffffffu, sum1, 2);
                l[mt][0] = l[mt][0] * f0 + sum0;  m[mt][0] = nm0;
                l[mt][1] = l[mt][1] * f1 + sum1;  m[mt][1] = nm1;
                #pragma unroll
                for (int nt = 0; nt < 8; nt++) {
                    o[mt][nt].x *= f0; o[mt][nt].y *= f0;
                    o[mt][nt].z *= f1; o[mt][nt].w *= f1;
                }
            }
            __syncwarp();   // Ps rows are warp-private

            // ---- O += P @ V ----
            #pragma unroll
            for (int kk = 0; kk < 4; kk++) {
                uint32_t af[2][4];
                #pragma unroll
                for (int mt = 0; mt < 2; mt++) {
                    uint32_t ad = pbase + (warp * 32 + mt * 16 + a_row) * 144
                                        + kk * 32 + a_col;
                    LDSM_X4(af[mt][0], af[mt][1], af[mt][2], af[mt][3], ad);
                }
                #pragma unroll
                for (int nt = 0; nt < 8; nt++) {
                    uint32_t bf[2];
                    uint32_t va = vbase +
                        ((kk * 16 + (lane & 15)) * VST + nt * 4) * 4;
                    ldsm_x2_trans(bf[0], bf[1], va);
                    mma_f16(o[0][nt], af[0], bf);
                    mma_f16(o[1][nt], af[1], bf);
                }
            }
        }
    }

    // ---- Epilogue: fp16 output ----
    #pragma unroll
    for (int mt = 0; mt < 2; mt++) {
        float inv0 = 1.0f / l[mt][0], inv1 = 1.0f / l[mt][1];
        int r = qt * 128 + warp * 32 + mt * 16 + g;
        #pragma unroll
        for (int nt = 0; nt < 8; nt++) {
            int col = h * 64 + nt * 8 + i4 * 2;
            *(uint32_t*)&out[((size_t)(b * kNT + r)) * 1024 + col] =
                packh2(o[mt][nt].x * inv0, o[mt][nt].y * inv0);
            *(uint32_t*)&out[((size_t)(b * kNT + r + 8)) * 1024 + col] =
                packh2(o[mt][nt].z * inv1, o[mt][nt].w * inv1);
        }
    }
}

// ---------------------------------------------------------------------------
// Launch
// ---------------------------------------------------------------------------
extern "C" void kernel_launch(void* const* d_in, const int* in_sizes, int n_in,
                              void* d_out, int out_size)
{
    const float* x      = (const float*)d_in[0];
    const float* rope   = (const float*)d_in[1];
    const float* W_attn = (const float*)d_in[2];
    const float* W_proj = (const float*)d_in[3];
    float* out = (float*)d_out;

    __half* qkv;  cudaGetSymbolAddress((void**)&qkv,  g_qkv);
    __half* attn; cudaGetSymbolAddress((void**)&attn, g_attn);
    __half* xh;   cudaGetSymbolAddress((void**)&xh,   g_xh);
    __half* wat;  cudaGetSymbolAddress((void**)&wat,  g_wat);
    __half* wpt;  cudaGetSymbolAddress((void**)&wpt,  g_wpt);

    cudaFuncSetAttribute(gemm_f16<true>,
                         cudaFuncAttributeMaxDynamicSharedMemorySize, GEMM_SMEM);
    cudaFuncSetAttribute(gemm_f16<false>,
                         cudaFuncAttributeMaxDynamicSharedMemorySize, GEMM_SMEM);
    cudaFuncSetAttribute(attn_f16,
                         cudaFuncAttributeMaxDynamicSharedMemorySize, ATTN_SMEM);

    // Prepass: x -> fp16; W_attn/W_proj -> fp16 transposed [n][k]
    cvt_h<<<(kNM * kND / 4) / 256, 256>>>(x, xh);
    transpose_h<<<dim3(3 * kND / 32, kND / 32), dim3(32, 8)>>>(W_attn, wat,
                                                               kND, 3 * kND);
    transpose_h<<<dim3(kND / 32, kND / 32), dim3(32, 8)>>>(W_proj, wpt,
                                                           kND, kND);

    // 1. QKV = x @ W_attn : fp16 out
    gemm_f16<true><<<dim3(3 * kND / 128, kNM / 128), 128, GEMM_SMEM>>>(
        xh, wat, qkv, kNM, 3 * kND, kND);

    // 2. Causal flash attention (RoPE fused), fp16 in/out
    attn_f16<<<dim3(kNT / 128, kNH, kNB), 128, ATTN_SMEM>>>(qkv, rope, attn);

    // 3. out = attn @ W_proj : fp32 out
    gemm_f16<false><<<dim3(kND / 128, kNM / 128), 128, GEMM_SMEM>>>(
        attn, wpt, out, kNM, kND, kND);
}

// round 10
// speedup vs baseline: 1.2700x; 1.0901x over previous
#include <cuda_runtime.h>
#include <cuda_fp16.h>
#include <cstdint>

// Problem constants
constexpr int kNB = 2;
constexpr int kNT = 2048;
constexpr int kND = 1024;
constexpr int kNH = 16;
constexpr int kNM = kNB * kNT;   // 4096 rows

// Scratch (allocation-free rule: device globals), all fp16
__device__ __half g_qkv[(size_t)kNM * 3 * kND];   // (4096, 3072) q,k pre-roped
__device__ __half g_attn[(size_t)kNM * kND];      // (4096, 1024)
__device__ __half g_xh[(size_t)kNM * kND];        // x -> fp16 [m][k]
__device__ __half g_wat[(size_t)3 * kND * kND];   // W_attn^T fp16 [n][k]
__device__ __half g_wpt[(size_t)kND * kND];       // W_proj^T fp16 [n][k]

// ---------------------------------------------------------------------------
// Helpers
// ---------------------------------------------------------------------------
__device__ __forceinline__ uint32_t packh2(float a, float b) {
    __half2 h = __floats2half2_rn(a, b);
    return *(uint32_t*)&h;
}

__device__ __forceinline__ void mma_f16(float4& c, const uint32_t a[4],
                                        const uint32_t b[2]) {
    asm volatile(
        "mma.sync.aligned.m16n8k16.row.col.f32.f16.f16.f32 "
        "{%0,%1,%2,%3}, {%4,%5,%6,%7}, {%8,%9}, {%0,%1,%2,%3};\n"
        : "+f"(c.x), "+f"(c.y), "+f"(c.z), "+f"(c.w)
        : "r"(a[0]), "r"(a[1]), "r"(a[2]), "r"(a[3]), "r"(b[0]), "r"(b[1]));
}

#define LDSM_X4(r0, r1, r2, r3, addr) \
    asm volatile("ldmatrix.sync.aligned.m8n8.x4.shared.b16 {%0,%1,%2,%3}, [%4];" \
                 : "=r"(r0), "=r"(r1), "=r"(r2), "=r"(r3) : "r"(addr))

__device__ __forceinline__ void ldsm_x2_trans(uint32_t& r0, uint32_t& r1,
                                              uint32_t saddr) {
    asm volatile("ldmatrix.sync.aligned.m8n8.x2.trans.shared.b16 {%0,%1}, [%2];"
                 : "=r"(r0), "=r"(r1) : "r"(saddr));
}

__device__ __forceinline__ unsigned sptr(const void* p) {
    return (unsigned)__cvta_generic_to_shared(p);
}
#define CP_ASYNC16(dst, src) \
    asm volatile("cp.async.cg.shared.global [%0], [%1], 16;" :: "r"(dst), "l"(src))
#define CP_COMMIT() asm volatile("cp.async.commit_group;")

// ---------------------------------------------------------------------------
// Prepass: fp32 -> fp16 conversion / transposed conversion
// ---------------------------------------------------------------------------
__global__ void cvt_h(const float* __restrict__ in, __half* __restrict__ out)
{
    int i = blockIdx.x * blockDim.x + threadIdx.x;
    float4 v = ((const float4*)in)[i];
    uint2 o;
    o.x = packh2(v.x, v.y);
    o.y = packh2(v.z, v.w);
    ((uint2*)out)[i] = o;
}

__global__ void transpose_h(const float* __restrict__ in, __half* __restrict__ out,
                            int R, int C)
{
    __shared__ float t[32][33];
    int c0 = blockIdx.x * 32, r0 = blockIdx.y * 32;
    for (int i = threadIdx.y; i < 32; i += 8)
        t[i][threadIdx.x] = in[(size_t)(r0 + i) * C + c0 + threadIdx.x];
    __syncthreads();
    for (int i = threadIdx.y; i < 32; i += 8)
        out[(size_t)(c0 + i) * R + r0 + threadIdx.x] = __float2half(t[threadIdx.x][i]);
}

// ---------------------------------------------------------------------------
// fp16 GEMM: C[M,N] = A[M,K] @ Bt[N,K]^T. 128x128 CTA, BK=64, 128 threads
// (4 warps 2x2), warp tile 64x64, ldmatrix.x4 loads, 3-stage cp.async ring.
// ROPE variant applies RoPE to cols<2048 (q,k) and 0.125 scale to cols<1024.
// ---------------------------------------------------------------------------
constexpr int GST = 36;                  // uints per smem row (64 fp16 + pad)
constexpr int GBUF = 2 * 128 * GST;      // uints per ring stage (A+B)
constexpr int GEMM_SMEM = 3 * GBUF * 4;  // 110592 B

template <bool HOUT, bool ROPE>
__global__ __launch_bounds__(128, 2) void gemm_f16(
    const __half* __restrict__ A, const __half* __restrict__ Bt,
    void* __restrict__ Cv, const float* __restrict__ rope,
    int M, int N, int K)
{
    extern __shared__ uint32_t gsh[];

    const int tid  = threadIdx.x;
    const int warp = tid >> 5, lane = tid & 31;
    const int g  = lane >> 2;
    const int i4 = lane & 3;
    const int wm = (warp >> 1) * 64;
    const int wn = (warp & 1) * 64;
    const int brow = blockIdx.y * 128;
    const int bcol = blockIdx.x * 128;
    const uint32_t sbase = sptr(gsh);

    const int a_row = lane & 15;
    const int a_col = (lane >> 4) * 16;
    const int b_row = (lane & 7) + ((lane >> 4) & 1) * 8;
    const int b_col = ((lane >> 3) & 1) * 16;

    float4 acc[4][8];
    #pragma unroll
    for (int mt = 0; mt < 4; mt++)
        #pragma unroll
        for (int nt = 0; nt < 8; nt++)
            acc[mt][nt] = make_float4(0.f, 0.f, 0.f, 0.f);

    const int NIT = K >> 6;   // BK=64

    auto stage = [&](int s, int buf) {
        uint32_t ab = sbase + buf * GBUF * 4;
        uint32_t bb = ab + 128 * GST * 4;
        const __half* Ag = A + (size_t)brow * K + (s << 6);
        const __half* Bg = Bt + (size_t)bcol * K + (s << 6);
        #pragma unroll
        for (int i = 0; i < 8; i++) {
            int id = tid + 128 * i;          // 0..1023
            int r = id >> 3, ch = id & 7;    // 128 rows x 8 16B-chunks
            CP_ASYNC16(ab + r * 144 + ch * 16, Ag + (size_t)r * K + ch * 8);
        }
        #pragma unroll
        for (int i = 0; i < 8; i++) {
            int id = tid + 128 * i;
            int r = id >> 3, ch = id & 7;
            CP_ASYNC16(bb + r * 144 + ch * 16, Bg + (size_t)r * K + ch * 8);
        }
        CP_COMMIT();
    };

    stage(0, 0);
    stage(1, 1);

    #pragma unroll 1
    for (int s = 0; s < NIT; s++) {
        const int b = s % 3;
        if (s < NIT - 1) { asm volatile("cp.async.wait_group 1;"); }
        else             { asm volatile("cp.async.wait_group 0;"); }
        __syncthreads();

        if (s + 2 < NIT) stage(s + 2, (s + 2) % 3);

        const uint32_t a_s = sbase + b * GBUF * 4;
        const uint32_t b_s = a_s + 128 * GST * 4;

        #pragma unroll
        for (int kk = 0; kk < 4; kk++) {
            uint32_t af[4][4], bf[8][2];
            #pragma unroll
            for (int mt = 0; mt < 4; mt++) {
                uint32_t ad = a_s + (wm + mt * 16 + a_row) * 144
                                  + kk * 32 + a_col;
                LDSM_X4(af[mt][0], af[mt][1], af[mt][2], af[mt][3], ad);
            }
            #pragma unroll
            for (int ntp = 0; ntp < 4; ntp++) {
                uint32_t bd = b_s + (wn + ntp * 16 + b_row) * 144
                                  + kk * 32 + b_col;
                LDSM_X4(bf[2 * ntp][0], bf[2 * ntp][1],
                        bf[2 * ntp + 1][0], bf[2 * ntp + 1][1], bd);
            }
            #pragma unroll
            for (int mt = 0; mt < 4; mt++)
                #pragma unroll
                for (int nt = 0; nt < 8; nt++)
                    mma_f16(acc[mt][nt], af[mt], bf[nt]);
        }
    }

    // Epilogue (RoPE fused for q,k columns when ROPE)
    #pragma unroll
    for (int mt = 0; mt < 4; mt++) {
        int row = brow + wm + mt * 16 + g;
        #pragma unroll
        for (int nt = 0; nt < 8; nt++) {
            int col = bcol + wn + nt * 8 + i4 * 2;
            float x0 = acc[mt][nt].x, x1 = acc[mt][nt].y;
            float z0 = acc[mt][nt].z, z1 = acc[mt][nt].w;
            if (ROPE && col < 2048) {
                int p = (col & 63) >> 1;
                int t0 = row & (kNT - 1);
                float c0 = rope[(t0 * 32 + p) * 2];
                float s0 = rope[(t0 * 32 + p) * 2 + 1];
                int t1 = (row + 8) & (kNT - 1);
                float c1 = rope[(t1 * 32 + p) * 2];
                float s1 = rope[(t1 * 32 + p) * 2 + 1];
                float nx0 = x0 * c0 - x1 * s0, nx1 = x1 * c0 + x0 * s0;
                float nz0 = z0 * c1 - z1 * s1, nz1 = z1 * c1 + z0 * s1;
                if (col < 1024) {   // q: fold 1/sqrt(HD)
                    nx0 *= 0.125f; nx1 *= 0.125f;
                    nz0 *= 0.125f; nz1 *= 0.125f;
                }
                x0 = nx0; x1 = nx1; z0 = nz0; z1 = nz1;
            }
            if (HOUT) {
                __half* C = (__half*)Cv;
                *(uint32_t*)&C[(size_t)row * N + col] = packh2(x0, x1);
                *(uint32_t*)&C[(size_t)(row + 8) * N + col] = packh2(z0, z1);
            } else {
                float* C = (float*)Cv;
                *(float2*)&C[(size_t)row * N + col] = make_float2(x0, x1);
                *(float2*)&C[(size_t)(row + 8) * N + col] = make_float2(z0, z1);
            }
        }
    }
}

// ---------------------------------------------------------------------------
// Flash attention, fp16 MMA. BM=128 (4 warps x m32), BN=64, HD=64, causal,
// 128 threads. Q/K pre-roped+scaled by the QKV GEMM epilogue, so all tile
// loads are pure cp.async; K/V stream through a 3-stage ring.
// ---------------------------------------------------------------------------
constexpr int AST = 36;   // uints per smem row (64 fp16 + pad)
constexpr int ATTN_SMEM =
    (128 * AST + 3 * 2 * 64 * AST + 128 * AST) * 4;   // 92160 B

__global__ __launch_bounds__(128, 2) void attn_f16(
    const __half* __restrict__ qkv, __half* __restrict__ out)
{
    extern __shared__ uint32_t ash[];
    uint32_t* Qs   = ash;                       // [128 m][AST]
    uint32_t* Ring = Qs + 128 * AST;            // 3 x (K[64][AST] + V[64][AST])
    uint32_t* Ps   = Ring + 3 * 2 * 64 * AST;   // [128 m][AST]

    const int tid  = threadIdx.x;
    const int warp = tid >> 5, lane = tid & 31;
    const int g  = lane >> 2;
    const int i4 = lane & 3;
    const int qt = gridDim.x - 1 - blockIdx.x;   // big tiles first
    const int h  = blockIdx.y;
    const int b  = blockIdx.z;
    const uint32_t qbase = sptr(Qs);
    const uint32_t rbase = sptr(Ring);
    const uint32_t pbase = sptr(Ps);

    const int a_row = lane & 15;
    const int a_col = (lane >> 4) * 16;
    const int b_row = (lane & 7) + ((lane >> 4) & 1) * 8;
    const int b_col = ((lane >> 3) & 1) * 16;

    const __half* qg = qkv + ((size_t)(b * kNT + qt * 128)) * 3072 + h * 64;

    // ---- Q tile via cp.async (pre-roped, pre-scaled) ----
    #pragma unroll
    for (int i = 0; i < 8; i++) {
        int id = tid + 128 * i;          // 0..1023
        int r = id >> 3, ch = id & 7;
        CP_ASYNC16(qbase + r * 144 + ch * 16, qg + (size_t)r * 3072 + ch * 8);
    }
    CP_COMMIT();

    const int nkt = 2 * qt + 2;
    auto stage = [&](int kt, int buf) {
        uint32_t kb = rbase + buf * 2 * 64 * AST * 4;
        uint32_t vb = kb + 64 * AST * 4;
        const __half* kg = qkv + ((size_t)(b * kNT + kt * 64)) * 3072
                               + h * 64 + 1024;
        #pragma unroll
        for (int i = 0; i < 4; i++) {
            int id = tid + 128 * i;      // 0..511
            int r = id >> 3, ch = id & 7;
            CP_ASYNC16(kb + r * 144 + ch * 16, kg + (size_t)r * 3072 + ch * 8);
            CP_ASYNC16(vb + r * 144 + ch * 16,
                       kg + 1024 + (size_t)r * 3072 + ch * 8);
        }
        CP_COMMIT();
    };

    stage(0, 0);
    stage(1, 1);

    // Wait for Q (2 stages may remain pending), then hoist Q fragments.
    asm volatile("cp.async.wait_group 2;");
    __syncthreads();

    uint32_t qf[2][4][4];
    #pragma unroll
    for (int mt = 0; mt < 2; mt++)
        #pragma unroll
        for (int kk = 0; kk < 4; kk++) {
            uint32_t ad = qbase + (warp * 32 + mt * 16 + a_row) * 144
                               + kk * 32 + a_col;
            LDSM_X4(qf[mt][kk][0], qf[mt][kk][1], qf[mt][kk][2], qf[mt][kk][3], ad);
        }

    float m[2][2], l[2][2];
    #pragma unroll
    for (int mt = 0; mt < 2; mt++) {
        m[mt][0] = m[mt][1] = -1e30f;
        l[mt][0] = l[mt][1] = 0.f;
    }
    float4 o[2][8];
    #pragma unroll
    for (int mt = 0; mt < 2; mt++)
        #pragma unroll
        for (int nt = 0; nt < 8; nt++)
            o[mt][nt] = make_float4(0.f, 0.f, 0.f, 0.f);

    #pragma unroll 1
    for (int kt = 0; kt < nkt; kt++) {
        if (kt < nkt - 1) { asm volatile("cp.async.wait_group 1;"); }
        else              { asm volatile("cp.async.wait_group 0;"); }
        __syncthreads();   // stage(kt) visible to all; compute kt-1 done by all

        if (kt + 2 < nkt) stage(kt + 2, (kt + 2) % 3);

        const uint32_t kb = rbase + (kt % 3) * 2 * 64 * AST * 4;
        const uint32_t vb = kb + 64 * AST * 4;

        // Warps whose rows are entirely left of this key tile skip compute.
        if (kt * 64 <= qt * 128 + warp * 32 + 31) {
            // ---- S = Q @ K^T ----
            float4 s[2][8];
            #pragma unroll
            for (int mt = 0; mt < 2; mt++)
                #pragma unroll
                for (int nt = 0; nt < 8; nt++)
                    s[mt][nt] = make_float4(0.f, 0.f, 0.f, 0.f);

            #pragma unroll
            for (int kk = 0; kk < 4; kk++) {
                uint32_t bf[8][2];
                #pragma unroll
                for (int ntp = 0; ntp < 4; ntp++) {
                    uint32_t bd = kb + (ntp * 16 + b_row) * 144
                                     + kk * 32 + b_col;
                    LDSM_X4(bf[2 * ntp][0], bf[2 * ntp][1],
                            bf[2 * ntp + 1][0], bf[2 * ntp + 1][1], bd);
                }
                #pragma unroll
                for (int nt = 0; nt < 8; nt++) {
                    mma_f16(s[0][nt], qf[0][kk], bf[nt]);
                    mma_f16(s[1][nt], qf[1][kk], bf[nt]);
                }
            }

            // ---- Causal mask ----
            if (kt >= 2 * qt) {
                #pragma unroll
                for (int mt = 0; mt < 2; mt++) {
                    int r0 = qt * 128 + warp * 32 + mt * 16 + g;
                    #pragma unroll
                    for (int nt = 0; nt < 8; nt++) {
                        int c0 = kt * 64 + nt * 8 + i4 * 2;
                        if (c0     > r0)     s[mt][nt].x = -1e30f;
                        if (c0 + 1 > r0)     s[mt][nt].y = -1e30f;
                        if (c0     > r0 + 8) s[mt][nt].z = -1e30f;
                        if (c0 + 1 > r0 + 8) s[mt][nt].w = -1e30f;
                    }
                }
            }

            // ---- Online softmax + P store (fp16, warp-private rows) ----
            #pragma unroll
            for (int mt = 0; mt < 2; mt++) {
                float mx0 = -1e30f, mx1 = -1e30f;
                #pragma unroll
                for (int nt = 0; nt < 8; nt++) {
                    mx0 = fmaxf(mx0, fmaxf(s[mt][nt].x, s[mt][nt].y));
                    mx1 = fmaxf(mx1, fmaxf(s[mt][nt].z, s[mt][nt].w));
                }
                mx0 = fmaxf(mx0, __shfl_xor_sync(0xffffffffu, mx0, 1));
                mx0 = fmaxf(mx0, __shfl_xor_sync(0xffffffffu, mx0, 2));
                mx1 = fmaxf(mx1, __shfl_xor_sync(0xffffffffu, mx1, 1));
                mx1 = fmaxf(mx1, __shfl_xor_sync(0xffffffffu, mx1, 2));
                float nm0 = fmaxf(m[mt][0], mx0), nm1 = fmaxf(m[mt][1], mx1);
                float f0 = __expf(m[mt][0] - nm0), f1 = __expf(m[mt][1] - nm1);
                float sum0 = 0.f, sum1 = 0.f;
                int r = warp * 32 + mt * 16 + g;
                #pragma unroll
                for (int nt = 0; nt < 8; nt++) {
                    float px = __expf(s[mt][nt].x - nm0);
                    float py = __expf(s[mt][nt].y - nm0);
                    float pz = __expf(s[mt][nt].z - nm1);
                    float pw = __expf(s[mt][nt].w - nm1);
                    sum0 += px + py;
                    sum1 += pz + pw;
                    Ps[r * AST + nt * 4 + i4]       = packh2(px, py);
                    Ps[(r + 8) * AST + nt * 4 + i4] = packh2(pz, pw);
                }
                sum0 += __shfl_xor_sync(0xffffffffu, sum0, 1);
                sum0 += __shfl_xor_sync(0xffffffffu, sum0, 2);
                sum1 += __shfl_xor_sync(0xffffffffu, sum1, 1);
                sum1 += __shfl_xor_sync(0xffffffffu, sum1, 2);
                l[mt][0] = l[mt][0] * f0 + sum0;  m[mt][0] = nm0;
                l[mt][1] = l[mt][1] * f1 + sum1;  m[mt][1] = nm1;
                #pragma unroll
                for (int nt = 0; nt < 8; nt++) {
                    o[mt][nt].x *= f0; o[mt][nt].y *= f0;
                    o[mt][nt].z *= f1; o[mt][nt].w *= f1;
                }
            }
            __syncwarp();   // Ps rows are warp-private

            // ---- O += P @ V ----
            #pragma unroll
            for (int kk = 0; kk < 4; kk++) {
                uint32_t af[2][4];
                #pragma unroll
                for (int mt = 0; mt < 2; mt++) {
                    uint32_t ad = pbase + (warp * 32 + mt * 16 + a_row) * 144
                                        + kk * 32 + a_col;
                    LDSM_X4(af[mt][0], af[mt][1], af[mt][2], af[mt][3], ad);
                }
                #pragma unroll
                for (int nt = 0; nt < 8; nt++) {
                    uint32_t bf[2];
                    uint32_t va = vb + (kk * 16 + (lane & 15)) * 144 + nt * 16;
                    ldsm_x2_trans(bf[0], bf[1], va);
                    mma_f16(o[0][nt], af[0], bf);
                    mma_f16(o[1][nt], af[1], bf);
                }
            }
        }
    }

    // ---- Epilogue: fp16 output ----
    #pragma unroll
    for (int mt = 0; mt < 2; mt++) {
        float inv0 = 1.0f / l[mt][0], inv1 = 1.0f / l[mt][1];
        int r = qt * 128 + warp * 32 + mt * 16 + g;
        #pragma unroll
        for (int nt = 0; nt < 8; nt++) {
            int col = h * 64 + nt * 8 + i4 * 2;
            *(uint32_t*)&out[((size_t)(b * kNT + r)) * 1024 + col] =
                packh2(o[mt][nt].x * inv0, o[mt][nt].y * inv0);
            *(uint32_t*)&out[((size_t)(b * kNT + r + 8)) * 1024 + col] =
                packh2(o[mt][nt].z * inv1, o[mt][nt].w * inv1);
        }
    }
}

// ---------------------------------------------------------------------------
// Launch
// ---------------------------------------------------------------------------
extern "C" void kernel_launch(void* const* d_in, const int* in_sizes, int n_in,
                              void* d_out, int out_size)
{
    const float* x      = (const float*)d_in[0];
    const float* rope   = (const float*)d_in[1];
    const float* W_attn = (const float*)d_in[2];
    const float* W_proj = (const float*)d_in[3];
    float* out = (float*)d_out;

    __half* qkv;  cudaGetSymbolAddress((void**)&qkv,  g_qkv);
    __half* attn; cudaGetSymbolAddress((void**)&attn, g_attn);
    __half* xh;   cudaGetSymbolAddress((void**)&xh,   g_xh);
    __half* wat;  cudaGetSymbolAddress((void**)&wat,  g_wat);
    __half* wpt;  cudaGetSymbolAddress((void**)&wpt,  g_wpt);

    cudaFuncSetAttribute((const void*)gemm_f16<true, true>,
                         cudaFuncAttributeMaxDynamicSharedMemorySize, GEMM_SMEM);
    cudaFuncSetAttribute((const void*)gemm_f16<false, false>,
                         cudaFuncAttributeMaxDynamicSharedMemorySize, GEMM_SMEM);
    cudaFuncSetAttribute((const void*)attn_f16,
                         cudaFuncAttributeMaxDynamicSharedMemorySize, ATTN_SMEM);

    // Prepass: x -> fp16; W_attn/W_proj -> fp16 transposed [n][k]
    cvt_h<<<(kNM * kND / 4) / 256, 256>>>(x, xh);
    transpose_h<<<dim3(3 * kND / 32, kND / 32), dim3(32, 8)>>>(W_attn, wat,
                                                               kND, 3 * kND);
    transpose_h<<<dim3(kND / 32, kND / 32), dim3(32, 8)>>>(W_proj, wpt,
                                                           kND, kND);

    // 1. QKV = x @ W_attn, RoPE + q-scale fused into the epilogue
    gemm_f16<true, true><<<dim3(3 * kND / 128, kNM / 128), 128, GEMM_SMEM>>>(
        xh, wat, qkv, rope, kNM, 3 * kND, kND);

    // 2. Causal flash attention (pure-copy tile loads, cp.async ring)
    attn_f16<<<dim3(kNT / 128, kNH, kNB), 128, ATTN_SMEM>>>(qkv, attn);

    // 3. out = attn @ W_proj : fp32 out
    gemm_f16<false, false><<<dim3(kND / 128, kNM / 128), 128, GEMM_SMEM>>>(
        attn, wpt, out, nullptr, kNM, kND, kND);
}

// round 11
// speedup vs baseline: 1.2983x; 1.0223x over previous
#include <cuda_runtime.h>
#include <cuda_fp16.h>
#include <cstdint>

// Problem constants
constexpr int kNB = 2;
constexpr int kNT = 2048;
constexpr int kND = 1024;
constexpr int kNH = 16;
constexpr int kNM = kNB * kNT;   // 4096 rows

// Scratch (allocation-free rule: device globals), all fp16
__device__ __half g_qkv[(size_t)kNM * 3 * kND];   // (4096, 3072) q,k pre-roped
__device__ __half g_attn[(size_t)kNM * kND];      // (4096, 1024)
__device__ __half g_xh[(size_t)kNM * kND];        // x -> fp16 [m][k]
__device__ __half g_wat[(size_t)3 * kND * kND];   // W_attn^T fp16 [n][k]
__device__ __half g_wpt[(size_t)kND * kND];       // W_proj^T fp16 [n][k]

// ---------------------------------------------------------------------------
// Helpers
// ---------------------------------------------------------------------------
__device__ __forceinline__ uint32_t packh2(float a, float b) {
    __half2 h = __floats2half2_rn(a, b);
    return *(uint32_t*)&h;
}

__device__ __forceinline__ void mma_f16(float4& c, const uint32_t a[4],
                                        const uint32_t b[2]) {
    asm volatile(
        "mma.sync.aligned.m16n8k16.row.col.f32.f16.f16.f32 "
        "{%0,%1,%2,%3}, {%4,%5,%6,%7}, {%8,%9}, {%0,%1,%2,%3};\n"
        : "+f"(c.x), "+f"(c.y), "+f"(c.z), "+f"(c.w)
        : "r"(a[0]), "r"(a[1]), "r"(a[2]), "r"(a[3]), "r"(b[0]), "r"(b[1]));
}

#define LDSM_X4(r0, r1, r2, r3, addr) \
    asm volatile("ldmatrix.sync.aligned.m8n8.x4.shared.b16 {%0,%1,%2,%3}, [%4];" \
                 : "=r"(r0), "=r"(r1), "=r"(r2), "=r"(r3) : "r"(addr))

#define LDSM_X4_T(r0, r1, r2, r3, addr) \
    asm volatile("ldmatrix.sync.aligned.m8n8.x4.trans.shared.b16 {%0,%1,%2,%3}, [%4];" \
                 : "=r"(r0), "=r"(r1), "=r"(r2), "=r"(r3) : "r"(addr))

__device__ __forceinline__ unsigned sptr(const void* p) {
    return (unsigned)__cvta_generic_to_shared(p);
}
#define CP_ASYNC16(dst, src) \
    asm volatile("cp.async.cg.shared.global [%0], [%1], 16;" :: "r"(dst), "l"(src))
#define CP_COMMIT() asm volatile("cp.async.commit_group;")

// ---------------------------------------------------------------------------
// Prepass: fp32 -> fp16 conversion / transposed conversion
// ---------------------------------------------------------------------------
__global__ void cvt_h(const float* __restrict__ in, __half* __restrict__ out)
{
    int i = blockIdx.x * blockDim.x + threadIdx.x;
    float4 v = ((const float4*)in)[i];
    uint2 o;
    o.x = packh2(v.x, v.y);
    o.y = packh2(v.z, v.w);
    ((uint2*)out)[i] = o;
}

__global__ void transpose_h(const float* __restrict__ in, __half* __restrict__ out,
                            int R, int C)
{
    __shared__ float t[32][33];
    int c0 = blockIdx.x * 32, r0 = blockIdx.y * 32;
    for (int i = threadIdx.y; i < 32; i += 8)
        t[i][threadIdx.x] = in[(size_t)(r0 + i) * C + c0 + threadIdx.x];
    __syncthreads();
    for (int i = threadIdx.y; i < 32; i += 8)
        out[(size_t)(c0 + i) * R + r0 + threadIdx.x] = __float2half(t[threadIdx.x][i]);
}

// ---------------------------------------------------------------------------
// fp16 GEMM: C[M,N] = A[M,K] @ Bt[N,K]^T. 128x128 CTA, BK=32, 128 threads
// (4 warps 2x2), warp tile 64x64, ldmatrix.x4 loads, 3-stage cp.async ring.
// ROPE variant applies RoPE to cols<2048 (q,k) and 0.125 scale to cols<1024.
// ---------------------------------------------------------------------------
constexpr int RST  = 20;                 // uints per smem row (32 fp16 + pad)
constexpr int GBUF = 2 * 128 * RST;      // uints per buffer (A+B)
constexpr int GEMM_SMEM = 3 * GBUF * 4;  // 61440 B

template <bool HOUT, bool ROPE>
__global__ __launch_bounds__(128, 2) void gemm_f16(
    const __half* __restrict__ A, const __half* __restrict__ Bt,
    void* __restrict__ Cv, const float* __restrict__ rope,
    int M, int N, int K)
{
    extern __shared__ uint32_t gsh[];

    const int tid  = threadIdx.x;
    const int warp = tid >> 5, lane = tid & 31;
    const int g  = lane >> 2;
    const int i4 = lane & 3;
    const int wm = (warp >> 1) * 64;
    const int wn = (warp & 1) * 64;
    const int brow = blockIdx.y * 128;
    const int bcol = blockIdx.x * 128;
    const uint32_t sbase = sptr(gsh);

    // ldmatrix address components (bytes)
    const int a_row = lane & 15;
    const int a_col = (lane >> 4) * 16;
    const int b_row = (lane & 7) + ((lane >> 4) & 1) * 8;
    const int b_col = ((lane >> 3) & 1) * 16;

    float4 acc[4][8];
    #pragma unroll
    for (int mt = 0; mt < 4; mt++)
        #pragma unroll
        for (int nt = 0; nt < 8; nt++)
            acc[mt][nt] = make_float4(0.f, 0.f, 0.f, 0.f);

    const int NIT = K >> 5;   // BK=32

    auto stage = [&](int s, int buf) {
        uint32_t ab = sbase + buf * GBUF * 4;
        uint32_t bb = ab + 128 * RST * 4;
        const __half* Ag = A + (size_t)brow * K + (s << 5);
        const __half* Bg = Bt + (size_t)bcol * K + (s << 5);
        #pragma unroll
        for (int i = 0; i < 4; i++) {
            int id = tid + 128 * i;          // 0..511
            int r = id >> 2, ch = id & 3;    // 128 rows x 4 16B-chunks
            CP_ASYNC16(ab + r * 80 + ch * 16, Ag + (size_t)r * K + ch * 8);
            CP_ASYNC16(bb + r * 80 + ch * 16, Bg + (size_t)r * K + ch * 8);
        }
        CP_COMMIT();
    };

    stage(0, 0);
    stage(1, 1);

    #pragma unroll 1
    for (int s = 0; s < NIT; s++) {
        const int b = s % 3;
        if (s < NIT - 1) { asm volatile("cp.async.wait_group 1;"); }
        else             { asm volatile("cp.async.wait_group 0;"); }
        __syncthreads();

        if (s + 2 < NIT) stage(s + 2, (s + 2) % 3);

        const uint32_t a_s = sbase + b * GBUF * 4;
        const uint32_t b_s = a_s + 128 * RST * 4;

        #pragma unroll
        for (int kk = 0; kk < 2; kk++) {
            uint32_t af[4][4], bf[8][2];
            #pragma unroll
            for (int mt = 0; mt < 4; mt++) {
                uint32_t ad = a_s + (wm + mt * 16 + a_row) * 80
                                  + kk * 32 + a_col;
                LDSM_X4(af[mt][0], af[mt][1], af[mt][2], af[mt][3], ad);
            }
            #pragma unroll
            for (int ntp = 0; ntp < 4; ntp++) {
                uint32_t bd = b_s + (wn + ntp * 16 + b_row) * 80
                                  + kk * 32 + b_col;
                LDSM_X4(bf[2 * ntp][0], bf[2 * ntp][1],
                        bf[2 * ntp + 1][0], bf[2 * ntp + 1][1], bd);
            }
            #pragma unroll
            for (int mt = 0; mt < 4; mt++)
                #pragma unroll
                for (int nt = 0; nt < 8; nt++)
                    mma_f16(acc[mt][nt], af[mt], bf[nt]);
        }
    }

    // Epilogue (RoPE fused for q,k columns when ROPE; q also scaled)
    #pragma unroll
    for (int mt = 0; mt < 4; mt++) {
        int row = brow + wm + mt * 16 + g;
        #pragma unroll
        for (int nt = 0; nt < 8; nt++) {
            int col = bcol + wn + nt * 8 + i4 * 2;
            float x0 = acc[mt][nt].x, x1 = acc[mt][nt].y;
            float z0 = acc[mt][nt].z, z1 = acc[mt][nt].w;
            if (ROPE && col < 2048) {
                int p = (col & 63) >> 1;
                int t0 = row & (kNT - 1);
                float c0 = rope[(t0 * 32 + p) * 2];
                float s0 = rope[(t0 * 32 + p) * 2 + 1];
                int t1 = (row + 8) & (kNT - 1);
                float c1 = rope[(t1 * 32 + p) * 2];
                float s1 = rope[(t1 * 32 + p) * 2 + 1];
                float nx0 = x0 * c0 - x1 * s0, nx1 = x1 * c0 + x0 * s0;
                float nz0 = z0 * c1 - z1 * s1, nz1 = z1 * c1 + z0 * s1;
                if (col < 1024) {   // q: fold 1/sqrt(HD)
                    nx0 *= 0.125f; nx1 *= 0.125f;
                    nz0 *= 0.125f; nz1 *= 0.125f;
                }
                x0 = nx0; x1 = nx1; z0 = nz0; z1 = nz1;
            }
            if (HOUT) {
                __half* C = (__half*)Cv;
                *(uint32_t*)&C[(size_t)row * N + col] = packh2(x0, x1);
                *(uint32_t*)&C[(size_t)(row + 8) * N + col] = packh2(z0, z1);
            } else {
                float* C = (float*)Cv;
                *(float2*)&C[(size_t)row * N + col] = make_float2(x0, x1);
                *(float2*)&C[(size_t)(row + 8) * N + col] = make_float2(z0, z1);
            }
        }
    }
}

// ---------------------------------------------------------------------------
// Flash attention, fp16 MMA. BM=128 (4 warps x m32), BN=64, HD=64, causal,
// 128 threads. Q/K pre-roped+scaled by the QKV GEMM epilogue; pure cp.async
// tile loads through a 3-stage K/V ring. V fragments via ldmatrix.x4.trans.
// ---------------------------------------------------------------------------
constexpr int AST = 36;   // uints per smem row (64 fp16 + pad)
constexpr int ATTN_SMEM =
    (128 * AST + 3 * 2 * 64 * AST + 128 * AST) * 4;   // 92160 B

__global__ __launch_bounds__(128, 2) void attn_f16(
    const __half* __restrict__ qkv, __half* __restrict__ out)
{
    extern __shared__ uint32_t ash[];
    uint32_t* Qs   = ash;                       // [128 m][AST]
    uint32_t* Ring = Qs + 128 * AST;            // 3 x (K[64][AST] + V[64][AST])
    uint32_t* Ps   = Ring + 3 * 2 * 64 * AST;   // [128 m][AST]

    const int tid  = threadIdx.x;
    const int warp = tid >> 5, lane = tid & 31;
    const int g  = lane >> 2;
    const int i4 = lane & 3;
    const int qt = gridDim.x - 1 - blockIdx.x;   // big tiles first
    const int h  = blockIdx.y;
    const int b  = blockIdx.z;
    const uint32_t qbase = sptr(Qs);
    const uint32_t rbase = sptr(Ring);
    const uint32_t pbase = sptr(Ps);

    const int a_row = lane & 15;
    const int a_col = (lane >> 4) * 16;
    const int b_row = (lane & 7) + ((lane >> 4) & 1) * 8;
    const int b_col = ((lane >> 3) & 1) * 16;
    const int v_row = lane & 15;                 // x4.trans row within 16
    const int v_sel = (lane >> 4) & 1;           // x4.trans col-group select

    const __half* qg = qkv + ((size_t)(b * kNT + qt * 128)) * 3072 + h * 64;

    // ---- Q tile via cp.async (pre-roped, pre-scaled) ----
    #pragma unroll
    for (int i = 0; i < 8; i++) {
        int id = tid + 128 * i;          // 0..1023
        int r = id >> 3, ch = id & 7;
        CP_ASYNC16(qbase + r * 144 + ch * 16, qg + (size_t)r * 3072 + ch * 8);
    }
    CP_COMMIT();

    const int nkt = 2 * qt + 2;
    auto stage = [&](int kt, int buf) {
        uint32_t kb = rbase + buf * 2 * 64 * AST * 4;
        uint32_t vb = kb + 64 * AST * 4;
        const __half* kg = qkv + ((size_t)(b * kNT + kt * 64)) * 3072
                               + h * 64 + 1024;
        #pragma unroll
        for (int i = 0; i < 4; i++) {
            int id = tid + 128 * i;      // 0..511
            int r = id >> 3, ch = id & 7;
            CP_ASYNC16(kb + r * 144 + ch * 16, kg + (size_t)r * 3072 + ch * 8);
            CP_ASYNC16(vb + r * 144 + ch * 16,
                       kg + 1024 + (size_t)r * 3072 + ch * 8);
        }
        CP_COMMIT();
    };

    stage(0, 0);
    stage(1, 1);

    // Wait for Q (2 stages may remain pending), then hoist Q fragments.
    asm volatile("cp.async.wait_group 2;");
    __syncthreads();

    uint32_t qf[2][4][4];
    #pragma unroll
    for (int mt = 0; mt < 2; mt++)
        #pragma unroll
        for (int kk = 0; kk < 4; kk++) {
            uint32_t ad = qbase + (warp * 32 + mt * 16 + a_row) * 144
                               + kk * 32 + a_col;
            LDSM_X4(qf[mt][kk][0], qf[mt][kk][1], qf[mt][kk][2], qf[mt][kk][3], ad);
        }

    float m[2][2], l[2][2];
    #pragma unroll
    for (int mt = 0; mt < 2; mt++) {
        m[mt][0] = m[mt][1] = -1e30f;
        l[mt][0] = l[mt][1] = 0.f;
    }
    float4 o[2][8];
    #pragma unroll
    for (int mt = 0; mt < 2; mt++)
        #pragma unroll
        for (int nt = 0; nt < 8; nt++)
            o[mt][nt] = make_float4(0.f, 0.f, 0.f, 0.f);

    #pragma unroll 1
    for (int kt = 0; kt < nkt; kt++) {
        if (kt < nkt - 1) { asm volatile("cp.async.wait_group 1;"); }
        else              { asm volatile("cp.async.wait_group 0;"); }
        __syncthreads();   // stage(kt) visible to all; compute kt-1 done by all

        if (kt + 2 < nkt) stage(kt + 2, (kt + 2) % 3);

        const uint32_t kb = rbase + (kt % 3) * 2 * 64 * AST * 4;
        const uint32_t vb = kb + 64 * AST * 4;

        // Warps whose rows are entirely left of this key tile skip compute.
        if (kt * 64 <= qt * 128 + warp * 32 + 31) {
            // ---- S = Q @ K^T ----
            float4 s[2][8];
            #pragma unroll
            for (int mt = 0; mt < 2; mt++)
                #pragma unroll
                for (int nt = 0; nt < 8; nt++)
                    s[mt][nt] = make_float4(0.f, 0.f, 0.f, 0.f);

            #pragma unroll
            for (int kk = 0; kk < 4; kk++) {
                uint32_t bf[8][2];
                #pragma unroll
                for (int ntp = 0; ntp < 4; ntp++) {
                    uint32_t bd = kb + (ntp * 16 + b_row) * 144
                                     + kk * 32 + b_col;
                    LDSM_X4(bf[2 * ntp][0], bf[2 * ntp][1],
                            bf[2 * ntp + 1][0], bf[2 * ntp + 1][1], bd);
                }
                #pragma unroll
                for (int nt = 0; nt < 8; nt++) {
                    mma_f16(s[0][nt], qf[0][kk], bf[nt]);
                    mma_f16(s[1][nt], qf[1][kk], bf[nt]);
                }
            }

            // ---- Causal mask ----
            if (kt >= 2 * qt) {
                #pragma unroll
                for (int mt = 0; mt < 2; mt++) {
                    int r0 = qt * 128 + warp * 32 + mt * 16 + g;
                    #pragma unroll
                    for (int nt = 0; nt < 8; nt++) {
                        int c0 = kt * 64 + nt * 8 + i4 * 2;
                        if (c0     > r0)     s[mt][nt].x = -1e30f;
                        if (c0 + 1 > r0)     s[mt][nt].y = -1e30f;
                        if (c0     > r0 + 8) s[mt][nt].z = -1e30f;
                        if (c0 + 1 > r0 + 8) s[mt][nt].w = -1e30f;
                    }
                }
            }

            // ---- Online softmax + P store (fp16, warp-private rows) ----
            #pragma unroll
            for (int mt = 0; mt < 2; mt++) {
                float mx0 = -1e30f, mx1 = -1e30f;
                #pragma unroll
                for (int nt = 0; nt < 8; nt++) {
                    mx0 = fmaxf(mx0, fmaxf(s[mt][nt].x, s[mt][nt].y));
                    mx1 = fmaxf(mx1, fmaxf(s[mt][nt].z, s[mt][nt].w));
                }
                mx0 = fmaxf(mx0, __shfl_xor_sync(0xffffffffu, mx0, 1));
                mx0 = fmaxf(mx0, __shfl_xor_sync(0xffffffffu, mx0, 2));
                mx1 = fmaxf(mx1, __shfl_xor_sync(0xffffffffu, mx1, 1));
                mx1 = fmaxf(mx1, __shfl_xor_sync(0xffffffffu, mx1, 2));
                float nm0 = fmaxf(m[mt][0], mx0), nm1 = fmaxf(m[mt][1], mx1);
                float f0 = __expf(m[mt][0] - nm0), f1 = __expf(m[mt][1] - nm1);
                float sum0 = 0.f, sum1 = 0.f;
                int r = warp * 32 + mt * 16 + g;
                #pragma unroll
                for (int nt = 0; nt < 8; nt++) {
                    float px = __expf(s[mt][nt].x - nm0);
                    float py = __expf(s[mt][nt].y - nm0);
                    float pz = __expf(s[mt][nt].z - nm1);
                    float pw = __expf(s[mt][nt].w - nm1);
                    sum0 += px + py;
                    sum1 += pz + pw;
                    Ps[r * AST + nt * 4 + i4]       = packh2(px, py);
                    Ps[(r + 8) * AST + nt * 4 + i4] = packh2(pz, pw);
                }
                sum0 += __shfl_xor_sync(0xffffffffu, sum0, 1);
                sum0 += __shfl_xor_sync(0xffffffffu, sum0, 2);
                sum1 += __shfl_xor_sync(0xffffffffu, sum1, 1);
                sum1 += __shfl_xor_sync(0xffffffffu, sum1, 2);
                l[mt][0] = l[mt][0] * f0 + sum0;  m[mt][0] = nm0;
                l[mt][1] = l[mt][1] * f1 + sum1;  m[mt][1] = nm1;
                #pragma unroll
                for (int nt = 0; nt < 8; nt++) {
                    o[mt][nt].x *= f0; o[mt][nt].y *= f0;
                    o[mt][nt].z *= f1; o[mt][nt].w *= f1;
                }
            }
            __syncwarp();   // Ps rows are warp-private

            // ---- O += P @ V (V via ldmatrix.x4.trans: 2 nt per op) ----
            #pragma unroll
            for (int kk = 0; kk < 4; kk++) {
                uint32_t af[2][4];
                #pragma unroll
                for (int mt = 0; mt < 2; mt++) {
                    uint32_t ad = pbase + (warp * 32 + mt * 16 + a_row) * 144
                                        + kk * 32 + a_col;
                    LDSM_X4(af[mt][0], af[mt][1], af[mt][2], af[mt][3], ad);
                }
                uint32_t bf[8][2];
                #pragma unroll
                for (int ntp = 0; ntp < 4; ntp++) {
                    uint32_t va = vb + (kk * 16 + v_row) * 144
                                     + (2 * ntp + v_sel) * 16;
                    LDSM_X4_T(bf[2 * ntp][0], bf[2 * ntp][1],
                              bf[2 * ntp + 1][0], bf[2 * ntp + 1][1], va);
                }
                #pragma unroll
                for (int nt = 0; nt < 8; nt++) {
                    mma_f16(o[0][nt], af[0], bf[nt]);
                    mma_f16(o[1][nt], af[1], bf[nt]);
                }
            }
        }
    }

    // ---- Epilogue: fp16 output ----
    #pragma unroll
    for (int mt = 0; mt < 2; mt++) {
        float inv0 = 1.0f / l[mt][0], inv1 = 1.0f / l[mt][1];
        int r = qt * 128 + warp * 32 + mt * 16 + g;
        #pragma unroll
        for (int nt = 0; nt < 8; nt++) {
            int col = h * 64 + nt * 8 + i4 * 2;
            *(uint32_t*)&out[((size_t)(b * kNT + r)) * 1024 + col] =
                packh2(o[mt][nt].x * inv0, o[mt][nt].y * inv0);
            *(uint32_t*)&out[((size_t)(b * kNT + r + 8)) * 1024 + col] =
                packh2(o[mt][nt].z * inv1, o[mt][nt].w * inv1);
        }
    }
}

// ---------------------------------------------------------------------------
// Launch
// ---------------------------------------------------------------------------
extern "C" void kernel_launch(void* const* d_in, const int* in_sizes, int n_in,
                              void* d_out, int out_size)
{
    const float* x      = (const float*)d_in[0];
    const float* rope   = (const float*)d_in[1];
    const float* W_attn = (const float*)d_in[2];
    const float* W_proj = (const float*)d_in[3];
    float* out = (float*)d_out;

    __half* qkv;  cudaGetSymbolAddress((void**)&qkv,  g_qkv);
    __half* attn; cudaGetSymbolAddress((void**)&attn, g_attn);
    __half* xh;   cudaGetSymbolAddress((void**)&xh,   g_xh);
    __half* wat;  cudaGetSymbolAddress((void**)&wat,  g_wat);
    __half* wpt;  cudaGetSymbolAddress((void**)&wpt,  g_wpt);

    cudaFuncSetAttribute((const void*)gemm_f16<true, true>,
                         cudaFuncAttributeMaxDynamicSharedMemorySize, GEMM_SMEM);
    cudaFuncSetAttribute((const void*)gemm_f16<false, false>,
                         cudaFuncAttributeMaxDynamicSharedMemorySize, GEMM_SMEM);
    cudaFuncSetAttribute((const void*)attn_f16,
                         cudaFuncAttributeMaxDynamicSharedMemorySize, ATTN_SMEM);

    // Prepass: x -> fp16; W_attn/W_proj -> fp16 transposed [n][k]
    cvt_h<<<(kNM * kND / 4) / 256, 256>>>(x, xh);
    transpose_h<<<dim3(3 * kND / 32, kND / 32), dim3(32, 8)>>>(W_attn, wat,
                                                               kND, 3 * kND);
    transpose_h<<<dim3(kND / 32, kND / 32), dim3(32, 8)>>>(W_proj, wpt,
                                                           kND, kND);

    // 1. QKV = x @ W_attn, RoPE + q-scale fused into the epilogue (BK=32)
    gemm_f16<true, true><<<dim3(3 * kND / 128, kNM / 128), 128, GEMM_SMEM>>>(
        xh, wat, qkv, rope, kNM, 3 * kND, kND);

    // 2. Causal flash attention (pure-copy tile loads, cp.async ring)
    attn_f16<<<dim3(kNT / 128, kNH, kNB), 128, ATTN_SMEM>>>(qkv, attn);

    // 3. out = attn @ W_proj : fp32 out
    gemm_f16<false, false><<<dim3(kND / 128, kNM / 128), 128, GEMM_SMEM>>>(
        attn, wpt, out, nullptr, kNM, kND, kND);
}

// round 12
// speedup vs baseline: 1.4062x; 1.0831x over previous
#include <cuda_runtime.h>
#include <cuda_fp16.h>
#include <cstdint>

// Problem constants
constexpr int kNB = 2;
constexpr int kNT = 2048;
constexpr int kND = 1024;
constexpr int kNH = 16;
constexpr int kNM = kNB * kNT;   // 4096 rows

// Scratch (allocation-free rule: device globals), all fp16
__device__ __half g_qkv[(size_t)kNM * 3 * kND];   // (4096, 3072)
__device__ __half g_attn[(size_t)kNM * kND];      // (4096, 1024)
__device__ __half g_xh[(size_t)kNM * kND];        // x -> fp16 [m][k]
__device__ __half g_wat[(size_t)3 * kND * kND];   // W_attn^T fp16 [n][k]
__device__ __half g_wpt[(size_t)kND * kND];       // W_proj^T fp16 [n][k]

// ---------------------------------------------------------------------------
// Helpers
// ---------------------------------------------------------------------------
__device__ __forceinline__ uint32_t packh2(float a, float b) {
    __half2 h = __floats2half2_rn(a, b);
    return *(uint32_t*)&h;
}

__device__ __forceinline__ void mma_f16(float4& c, const uint32_t a[4],
                                        const uint32_t b[2]) {
    asm volatile(
        "mma.sync.aligned.m16n8k16.row.col.f32.f16.f16.f32 "
        "{%0,%1,%2,%3}, {%4,%5,%6,%7}, {%8,%9}, {%0,%1,%2,%3};\n"
        : "+f"(c.x), "+f"(c.y), "+f"(c.z), "+f"(c.w)
        : "r"(a[0]), "r"(a[1]), "r"(a[2]), "r"(a[3]), "r"(b[0]), "r"(b[1]));
}

#define LDSM_X4(r0, r1, r2, r3, addr) \
    asm volatile("ldmatrix.sync.aligned.m8n8.x4.shared.b16 {%0,%1,%2,%3}, [%4];" \
                 : "=r"(r0), "=r"(r1), "=r"(r2), "=r"(r3) : "r"(addr))

#define LDSM_X4_T(r0, r1, r2, r3, addr) \
    asm volatile("ldmatrix.sync.aligned.m8n8.x4.trans.shared.b16 {%0,%1,%2,%3}, [%4];" \
                 : "=r"(r0), "=r"(r1), "=r"(r2), "=r"(r3) : "r"(addr))

__device__ __forceinline__ unsigned sptr(const void* p) {
    return (unsigned)__cvta_generic_to_shared(p);
}
#define CP_ASYNC16(dst, src) \
    asm volatile("cp.async.cg.shared.global [%0], [%1], 16;" :: "r"(dst), "l"(src))
#define CP_COMMIT() asm volatile("cp.async.commit_group;")

// ---------------------------------------------------------------------------
// Prepass kernels
// ---------------------------------------------------------------------------
__global__ void cvt_h(const float* __restrict__ in, __half* __restrict__ out)
{
    int i = blockIdx.x * blockDim.x + threadIdx.x;
    float4 v = ((const float4*)in)[i];
    uint2 o;
    o.x = packh2(v.x, v.y);
    o.y = packh2(v.z, v.w);
    ((uint2*)out)[i] = o;
}

__global__ void transpose_h(const float* __restrict__ in, __half* __restrict__ out,
                            int R, int C)
{
    __shared__ float t[32][33];
    int c0 = blockIdx.x * 32, r0 = blockIdx.y * 32;
    for (int i = threadIdx.y; i < 32; i += 8)
        t[i][threadIdx.x] = in[(size_t)(r0 + i) * C + c0 + threadIdx.x];
    __syncthreads();
    for (int i = threadIdx.y; i < 32; i += 8)
        out[(size_t)(c0 + i) * R + r0 + threadIdx.x] = __float2half(t[threadIdx.x][i]);
}

// In-place RoPE on fp16 qkv (q scaled by 0.125). One thread per rotation pair.
__global__ void rope_h(__half* __restrict__ qkv, const float* __restrict__ rope)
{
    int idx = blockIdx.x * blockDim.x + threadIdx.x;  // over B*T*H*32
    int i = idx & 31;
    int h = (idx >> 5) & 15;
    int t = (idx >> 9) & (kNT - 1);
    int b = idx >> 20;

    float2 cs = ((const float2*)rope)[t * 32 + i];
    size_t base = ((size_t)(b * kNT + t)) * 3072 + h * 64 + 2 * i;

    uint32_t qv = *(uint32_t*)&qkv[base];
    __half2 qh = *(__half2*)&qv;
    float q0 = __low2float(qh), q1 = __high2float(qh);
    *(uint32_t*)&qkv[base] =
        packh2((q0 * cs.x - q1 * cs.y) * 0.125f,
               (q1 * cs.x + q0 * cs.y) * 0.125f);

    uint32_t kv = *(uint32_t*)&qkv[base + 1024];
    __half2 kh = *(__half2*)&kv;
    float k0 = __low2float(kh), k1 = __high2float(kh);
    *(uint32_t*)&qkv[base + 1024] =
        packh2(k0 * cs.x - k1 * cs.y, k1 * cs.x + k0 * cs.y);
}

// ---------------------------------------------------------------------------
// fp16 GEMM: C[M,N] = A[M,K] @ Bt[N,K]^T. 128x128 CTA, BK=32, 128 threads
// (4 warps 2x2), warp tile 64x64, ldmatrix.x4 loads, 3-stage cp.async ring.
// ---------------------------------------------------------------------------
constexpr int RST  = 20;                 // uints per smem row (32 fp16 + pad)
constexpr int GBUF = 2 * 128 * RST;      // uints per buffer (A+B)
constexpr int GEMM_SMEM = 3 * GBUF * 4;  // 61440 B

template <bool HOUT>
__global__ __launch_bounds__(128, 2) void gemm_f16(
    const __half* __restrict__ A, const __half* __restrict__ Bt,
    void* __restrict__ Cv, int M, int N, int K)
{
    extern __shared__ uint32_t gsh[];

    const int tid  = threadIdx.x;
    const int warp = tid >> 5, lane = tid & 31;
    const int g  = lane >> 2;
    const int i4 = lane & 3;
    const int wm = (warp >> 1) * 64;
    const int wn = (warp & 1) * 64;
    const int brow = blockIdx.y * 128;
    const int bcol = blockIdx.x * 128;
    const uint32_t sbase = sptr(gsh);

    const int a_row = lane & 15;
    const int a_col = (lane >> 4) * 16;
    const int b_row = (lane & 7) + ((lane >> 4) & 1) * 8;
    const int b_col = ((lane >> 3) & 1) * 16;

    float4 acc[4][8];
    #pragma unroll
    for (int mt = 0; mt < 4; mt++)
        #pragma unroll
        for (int nt = 0; nt < 8; nt++)
            acc[mt][nt] = make_float4(0.f, 0.f, 0.f, 0.f);

    const int NIT = K >> 5;   // BK=32

    auto stage = [&](int s, int buf) {
        uint32_t ab = sbase + buf * GBUF * 4;
        uint32_t bb = ab + 128 * RST * 4;
        const __half* Ag = A + (size_t)brow * K + (s << 5);
        const __half* Bg = Bt + (size_t)bcol * K + (s << 5);
        #pragma unroll
        for (int i = 0; i < 4; i++) {
            int id = tid + 128 * i;          // 0..511
            int r = id >> 2, ch = id & 3;    // 128 rows x 4 16B-chunks
            CP_ASYNC16(ab + r * 80 + ch * 16, Ag + (size_t)r * K + ch * 8);
            CP_ASYNC16(bb + r * 80 + ch * 16, Bg + (size_t)r * K + ch * 8);
        }
        CP_COMMIT();
    };

    stage(0, 0);
    stage(1, 1);

    #pragma unroll 1
    for (int s = 0; s < NIT; s++) {
        const int b = s % 3;
        if (s < NIT - 1) { asm volatile("cp.async.wait_group 1;"); }
        else             { asm volatile("cp.async.wait_group 0;"); }
        __syncthreads();

        if (s + 2 < NIT) stage(s + 2, (s + 2) % 3);

        const uint32_t a_s = sbase + b * GBUF * 4;
        const uint32_t b_s = a_s + 128 * RST * 4;

        #pragma unroll
        for (int kk = 0; kk < 2; kk++) {
            uint32_t af[4][4], bf[8][2];
            #pragma unroll
            for (int mt = 0; mt < 4; mt++) {
                uint32_t ad = a_s + (wm + mt * 16 + a_row) * 80
                                  + kk * 32 + a_col;
                LDSM_X4(af[mt][0], af[mt][1], af[mt][2], af[mt][3], ad);
            }
            #pragma unroll
            for (int ntp = 0; ntp < 4; ntp++) {
                uint32_t bd = b_s + (wn + ntp * 16 + b_row) * 80
                                  + kk * 32 + b_col;
                LDSM_X4(bf[2 * ntp][0], bf[2 * ntp][1],
                        bf[2 * ntp + 1][0], bf[2 * ntp + 1][1], bd);
            }
            #pragma unroll
            for (int mt = 0; mt < 4; mt++)
                #pragma unroll
                for (int nt = 0; nt < 8; nt++)
                    mma_f16(acc[mt][nt], af[mt], bf[nt]);
        }
    }

    // Epilogue
    #pragma unroll
    for (int mt = 0; mt < 4; mt++) {
        int row = brow + wm + mt * 16 + g;
        #pragma unroll
        for (int nt = 0; nt < 8; nt++) {
            int col = bcol + wn + nt * 8 + i4 * 2;
            if (HOUT) {
                __half* C = (__half*)Cv;
                *(uint32_t*)&C[(size_t)row * N + col] =
                    packh2(acc[mt][nt].x, acc[mt][nt].y);
                *(uint32_t*)&C[(size_t)(row + 8) * N + col] =
                    packh2(acc[mt][nt].z, acc[mt][nt].w);
            } else {
                float* C = (float*)Cv;
                *(float2*)&C[(size_t)row * N + col] =
                    make_float2(acc[mt][nt].x, acc[mt][nt].y);
                *(float2*)&C[(size_t)(row + 8) * N + col] =
                    make_float2(acc[mt][nt].z, acc[mt][nt].w);
            }
        }
    }
}

// ---------------------------------------------------------------------------
// Flash attention, fp16 MMA. BM=128 (4 warps x m32), BN=64, HD=64, causal,
// 128 threads. Q/K pre-roped+scaled; pure cp.async loads, 3-stage K/V ring.
// P kept in registers (S C-fragment == PV A-fragment layout). V via
// ldmatrix.x4.trans.
// ---------------------------------------------------------------------------
constexpr int AST = 36;   // uints per smem row (64 fp16 + pad)
constexpr int ATTN_SMEM = (128 * AST + 3 * 2 * 64 * AST) * 4;   // 73728 B

__global__ __launch_bounds__(128, 2) void attn_f16(
    const __half* __restrict__ qkv, __half* __restrict__ out)
{
    extern __shared__ uint32_t ash[];
    uint32_t* Qs   = ash;                       // [128 m][AST]
    uint32_t* Ring = Qs + 128 * AST;            // 3 x (K[64][AST] + V[64][AST])

    const int tid  = threadIdx.x;
    const int warp = tid >> 5, lane = tid & 31;
    const int g  = lane >> 2;
    const int i4 = lane & 3;
    const int qt = gridDim.x - 1 - blockIdx.x;   // big tiles first
    const int h  = blockIdx.y;
    const int b  = blockIdx.z;
    const uint32_t qbase = sptr(Qs);
    const uint32_t rbase = sptr(Ring);

    const int a_row = lane & 15;
    const int a_col = (lane >> 4) * 16;
    const int b_row = (lane & 7) + ((lane >> 4) & 1) * 8;
    const int b_col = ((lane >> 3) & 1) * 16;
    const int v_row = lane & 15;
    const int v_sel = (lane >> 4) & 1;

    const __half* qg = qkv + ((size_t)(b * kNT + qt * 128)) * 3072 + h * 64;

    // ---- Q tile via cp.async (pre-roped, pre-scaled) ----
    #pragma unroll
    for (int i = 0; i < 8; i++) {
        int id = tid + 128 * i;          // 0..1023
        int r = id >> 3, ch = id & 7;
        CP_ASYNC16(qbase + r * 144 + ch * 16, qg + (size_t)r * 3072 + ch * 8);
    }
    CP_COMMIT();

    const int nkt = 2 * qt + 2;
    auto stage = [&](int kt, int buf) {
        uint32_t kb = rbase + buf * 2 * 64 * AST * 4;
        uint32_t vb = kb + 64 * AST * 4;
        const __half* kg = qkv + ((size_t)(b * kNT + kt * 64)) * 3072
                               + h * 64 + 1024;
        #pragma unroll
        for (int i = 0; i < 4; i++) {
            int id = tid + 128 * i;      // 0..511
            int r = id >> 3, ch = id & 7;
            CP_ASYNC16(kb + r * 144 + ch * 16, kg + (size_t)r * 3072 + ch * 8);
            CP_ASYNC16(vb + r * 144 + ch * 16,
                       kg + 1024 + (size_t)r * 3072 + ch * 8);
        }
        CP_COMMIT();
    };

    stage(0, 0);
    stage(1, 1);

    // Wait for Q (2 stages may remain pending), then hoist Q fragments.
    asm volatile("cp.async.wait_group 2;");
    __syncthreads();

    uint32_t qf[2][4][4];
    #pragma unroll
    for (int mt = 0; mt < 2; mt++)
        #pragma unroll
        for (int kk = 0; kk < 4; kk++) {
            uint32_t ad = qbase + (warp * 32 + mt * 16 + a_row) * 144
                               + kk * 32 + a_col;
            LDSM_X4(qf[mt][kk][0], qf[mt][kk][1], qf[mt][kk][2], qf[mt][kk][3], ad);
        }

    float m[2][2], l[2][2];
    #pragma unroll
    for (int mt = 0; mt < 2; mt++) {
        m[mt][0] = m[mt][1] = -1e30f;
        l[mt][0] = l[mt][1] = 0.f;
    }
    float4 o[2][8];
    #pragma unroll
    for (int mt = 0; mt < 2; mt++)
        #pragma unroll
        for (int nt = 0; nt < 8; nt++)
            o[mt][nt] = make_float4(0.f, 0.f, 0.f, 0.f);

    #pragma unroll 1
    for (int kt = 0; kt < nkt; kt++) {
        if (kt < nkt - 1) { asm volatile("cp.async.wait_group 1;"); }
        else              { asm volatile("cp.async.wait_group 0;"); }
        __syncthreads();   // stage(kt) visible; compute on kt-1 done by all

        if (kt + 2 < nkt) stage(kt + 2, (kt + 2) % 3);

        const uint32_t kb = rbase + (kt % 3) * 2 * 64 * AST * 4;
        const uint32_t vb = kb + 64 * AST * 4;

        // Warps whose rows are entirely left of this key tile skip compute.
        if (kt * 64 <= qt * 128 + warp * 32 + 31) {
            // ---- S = Q @ K^T ----
            float4 s[2][8];
            #pragma unroll
            for (int mt = 0; mt < 2; mt++)
                #pragma unroll
                for (int nt = 0; nt < 8; nt++)
                    s[mt][nt] = make_float4(0.f, 0.f, 0.f, 0.f);

            #pragma unroll
            for (int kk = 0; kk < 4; kk++) {
                uint32_t bf[8][2];
                #pragma unroll
                for (int ntp = 0; ntp < 4; ntp++) {
                    uint32_t bd = kb + (ntp * 16 + b_row) * 144
                                     + kk * 32 + b_col;
                    LDSM_X4(bf[2 * ntp][0], bf[2 * ntp][1],
                            bf[2 * ntp + 1][0], bf[2 * ntp + 1][1], bd);
                }
                #pragma unroll
                for (int nt = 0; nt < 8; nt++) {
                    mma_f16(s[0][nt], qf[0][kk], bf[nt]);
                    mma_f16(s[1][nt], qf[1][kk], bf[nt]);
                }
            }

            // ---- Causal mask ----
            if (kt >= 2 * qt) {
                #pragma unroll
                for (int mt = 0; mt < 2; mt++) {
                    int r0 = qt * 128 + warp * 32 + mt * 16 + g;
                    #pragma unroll
                    for (int nt = 0; nt < 8; nt++) {
                        int c0 = kt * 64 + nt * 8 + i4 * 2;
                        if (c0     > r0)     s[mt][nt].x = -1e30f;
                        if (c0 + 1 > r0)     s[mt][nt].y = -1e30f;
                        if (c0     > r0 + 8) s[mt][nt].z = -1e30f;
                        if (c0 + 1 > r0 + 8) s[mt][nt].w = -1e30f;
                    }
                }
            }

            // ---- Online softmax; P packed directly into A-fragments ----
            uint32_t pf[2][8][2];   // [mt][nt][row-half]
            #pragma unroll
            for (int mt = 0; mt < 2; mt++) {
                float mx0 = -1e30f, mx1 = -1e30f;
                #pragma unroll
                for (int nt = 0; nt < 8; nt++) {
                    mx0 = fmaxf(mx0, fmaxf(s[mt][nt].x, s[mt][nt].y));
                    mx1 = fmaxf(mx1, fmaxf(s[mt][nt].z, s[mt][nt].w));
                }
                mx0 = fmaxf(mx0, __shfl_xor_sync(0xffffffffu, mx0, 1));
                mx0 = fmaxf(mx0, __shfl_xor_sync(0xffffffffu, mx0, 2));
                mx1 = fmaxf(mx1, __shfl_xor_sync(0xffffffffu, mx1, 1));
                mx1 = fmaxf(mx1, __shfl_xor_sync(0xffffffffu, mx1, 2));
                float nm0 = fmaxf(m[mt][0], mx0), nm1 = fmaxf(m[mt][1], mx1);
                float f0 = __expf(m[mt][0] - nm0), f1 = __expf(m[mt][1] - nm1);
                float sum0 = 0.f, sum1 = 0.f;
                #pragma unroll
                for (int nt = 0; nt < 8; nt++) {
                    float px = __expf(s[mt][nt].x - nm0);
                    float py = __expf(s[mt][nt].y - nm0);
                    float pz = __expf(s[mt][nt].z - nm1);
                    float pw = __expf(s[mt][nt].w - nm1);
                    sum0 += px + py;
                    sum1 += pz + pw;
                    pf[mt][nt][0] = packh2(px, py);
                    pf[mt][nt][1] = packh2(pz, pw);
                }
                sum0 += __shfl_xor_sync(0xffffffffu, sum0, 1);
                sum0 += __shfl_xor_sync(0xffffffffu, sum0, 2);
                sum1 += __shfl_xor_sync(0xffffffffu, sum1, 1);
                sum1 += __shfl_xor_sync(0xffffffffu, sum1, 2);
                l[mt][0] = l[mt][0] * f0 + sum0;  m[mt][0] = nm0;
                l[mt][1] = l[mt][1] * f1 + sum1;  m[mt][1] = nm1;
                #pragma unroll
                for (int nt = 0; nt < 8; nt++) {
                    o[mt][nt].x *= f0; o[mt][nt].y *= f0;
                    o[mt][nt].z *= f1; o[mt][nt].w *= f1;
                }
            }

            // ---- O += P @ V (P from registers; V via ldmatrix.x4.trans) ----
            #pragma unroll
            for (int kk = 0; kk < 4; kk++) {
                uint32_t af[2][4];
                #pragma unroll
                for (int mt = 0; mt < 2; mt++) {
                    af[mt][0] = pf[mt][2 * kk][0];
                    af[mt][1] = pf[mt][2 * kk][1];
                    af[mt][2] = pf[mt][2 * kk + 1][0];
                    af[mt][3] = pf[mt][2 * kk + 1][1];
                }
                uint32_t bf[8][2];
                #pragma unroll
                for (int ntp = 0; ntp < 4; ntp++) {
                    uint32_t va = vb + (kk * 16 + v_row) * 144
                                     + (2 * ntp + v_sel) * 16;
                    LDSM_X4_T(bf[2 * ntp][0], bf[2 * ntp][1],
                              bf[2 * ntp + 1][0], bf[2 * ntp + 1][1], va);
                }
                #pragma unroll
                for (int nt = 0; nt < 8; nt++) {
                    mma_f16(o[0][nt], af[0], bf[nt]);
                    mma_f16(o[1][nt], af[1], bf[nt]);
                }
            }
        }
    }

    // ---- Epilogue: fp16 output ----
    #pragma unroll
    for (int mt = 0; mt < 2; mt++) {
        float inv0 = 1.0f / l[mt][0], inv1 = 1.0f / l[mt][1];
        int r = qt * 128 + warp * 32 + mt * 16 + g;
        #pragma unroll
        for (int nt = 0; nt < 8; nt++) {
            int col = h * 64 + nt * 8 + i4 * 2;
            *(uint32_t*)&out[((size_t)(b * kNT + r)) * 1024 + col] =
                packh2(o[mt][nt].x * inv0, o[mt][nt].y * inv0);
            *(uint32_t*)&out[((size_t)(b * kNT + r + 8)) * 1024 + col] =
                packh2(o[mt][nt].z * inv1, o[mt][nt].w * inv1);
        }
    }
}

// ---------------------------------------------------------------------------
// Launch
// ---------------------------------------------------------------------------
extern "C" void kernel_launch(void* const* d_in, const int* in_sizes, int n_in,
                              void* d_out, int out_size)
{
    const float* x      = (const float*)d_in[0];
    const float* rope   = (const float*)d_in[1];
    const float* W_attn = (const float*)d_in[2];
    const float* W_proj = (const float*)d_in[3];
    float* out = (float*)d_out;

    __half* qkv;  cudaGetSymbolAddress((void**)&qkv,  g_qkv);
    __half* attn; cudaGetSymbolAddress((void**)&attn, g_attn);
    __half* xh;   cudaGetSymbolAddress((void**)&xh,   g_xh);
    __half* wat;  cudaGetSymbolAddress((void**)&wat,  g_wat);
    __half* wpt;  cudaGetSymbolAddress((void**)&wpt,  g_wpt);

    cudaFuncSetAttribute((const void*)gemm_f16<true>,
                         cudaFuncAttributeMaxDynamicSharedMemorySize, GEMM_SMEM);
    cudaFuncSetAttribute((const void*)gemm_f16<false>,
                         cudaFuncAttributeMaxDynamicSharedMemorySize, GEMM_SMEM);
    cudaFuncSetAttribute((const void*)attn_f16,
                         cudaFuncAttributeMaxDynamicSharedMemorySize, ATTN_SMEM);

    // Prepass: x -> fp16; W_attn/W_proj -> fp16 transposed [n][k]
    cvt_h<<<(kNM * kND / 4) / 256, 256>>>(x, xh);
    transpose_h<<<dim3(3 * kND / 32, kND / 32), dim3(32, 8)>>>(W_attn, wat,
                                                               kND, 3 * kND);
    transpose_h<<<dim3(kND / 32, kND / 32), dim3(32, 8)>>>(W_proj, wpt,
                                                           kND, kND);

    // 1. QKV = x @ W_attn (clean GEMM, fp16 out)
    gemm_f16<true><<<dim3(3 * kND / 128, kNM / 128), 128, GEMM_SMEM>>>(
        xh, wat, qkv, kNM, 3 * kND, kND);

    // 2. RoPE in place on fp16 q,k (q also scaled by 1/sqrt(HD))
    rope_h<<<(kNB * kNT * kNH * 32) / 256, 256>>>(qkv, rope);

    // 3. Causal flash attention (P in registers, cp.async ring)
    attn_f16<<<dim3(kNT / 128, kNH, kNB), 128, ATTN_SMEM>>>(qkv, attn);

    // 4. out = attn @ W_proj : fp32 out
    gemm_f16<false><<<dim3(kND / 128, kNM / 128), 128, GEMM_SMEM>>>(
        attn, wpt, out, kNM, kND, kND);
}

// round 13
// speedup vs baseline: 1.4756x; 1.0494x over previous
#include <cuda_runtime.h>
#include <cuda_fp16.h>
#include <cstdint>

// Problem constants
constexpr int kNB = 2;
constexpr int kNT = 2048;
constexpr int kND = 1024;
constexpr int kNH = 16;
constexpr int kNM = kNB * kNT;   // 4096 rows

// Scratch (allocation-free rule: device globals), all fp16
__device__ __half g_qkv[(size_t)kNM * 3 * kND];   // (4096, 3072)
__device__ __half g_attn[(size_t)kNM * kND];      // (4096, 1024)
__device__ __half g_xh[(size_t)kNM * kND];        // x -> fp16 [m][k]
__device__ __half g_wat[(size_t)3 * kND * kND];   // W_attn^T fp16 [n][k]
__device__ __half g_wpt[(size_t)kND * kND];       // W_proj^T fp16 [n][k]

// ---------------------------------------------------------------------------
// Helpers
// ---------------------------------------------------------------------------
__device__ __forceinline__ uint32_t packh2(float a, float b) {
    __half2 h = __floats2half2_rn(a, b);
    return *(uint32_t*)&h;
}

__device__ __forceinline__ uint32_t h2exp2u(uint32_t a) {
    uint32_t d;
    asm("ex2.approx.f16x2 %0, %1;" : "=r"(d) : "r"(a));
    return d;
}

__device__ __forceinline__ void mma_f16(float4& c, const uint32_t a[4],
                                        const uint32_t b[2]) {
    asm volatile(
        "mma.sync.aligned.m16n8k16.row.col.f32.f16.f16.f32 "
        "{%0,%1,%2,%3}, {%4,%5,%6,%7}, {%8,%9}, {%0,%1,%2,%3};\n"
        : "+f"(c.x), "+f"(c.y), "+f"(c.z), "+f"(c.w)
        : "r"(a[0]), "r"(a[1]), "r"(a[2]), "r"(a[3]), "r"(b[0]), "r"(b[1]));
}

#define LDSM_X4(r0, r1, r2, r3, addr) \
    asm volatile("ldmatrix.sync.aligned.m8n8.x4.shared.b16 {%0,%1,%2,%3}, [%4];" \
                 : "=r"(r0), "=r"(r1), "=r"(r2), "=r"(r3) : "r"(addr))

#define LDSM_X4_T(r0, r1, r2, r3, addr) \
    asm volatile("ldmatrix.sync.aligned.m8n8.x4.trans.shared.b16 {%0,%1,%2,%3}, [%4];" \
                 : "=r"(r0), "=r"(r1), "=r"(r2), "=r"(r3) : "r"(addr))

__device__ __forceinline__ unsigned sptr(const void* p) {
    return (unsigned)__cvta_generic_to_shared(p);
}
#define CP_ASYNC16(dst, src) \
    asm volatile("cp.async.cg.shared.global [%0], [%1], 16;" :: "r"(dst), "l"(src))
#define CP_COMMIT() asm volatile("cp.async.commit_group;")

// ---------------------------------------------------------------------------
// Prepass kernels
// ---------------------------------------------------------------------------
__global__ void cvt_h(const float* __restrict__ in, __half* __restrict__ out)
{
    int i = blockIdx.x * blockDim.x + threadIdx.x;
    float4 v = ((const float4*)in)[i];
    uint2 o;
    o.x = packh2(v.x, v.y);
    o.y = packh2(v.z, v.w);
    ((uint2*)out)[i] = o;
}

__global__ void transpose_h(const float* __restrict__ in, __half* __restrict__ out,
                            int R, int C)
{
    __shared__ float t[32][33];
    int c0 = blockIdx.x * 32, r0 = blockIdx.y * 32;
    for (int i = threadIdx.y; i < 32; i += 8)
        t[i][threadIdx.x] = in[(size_t)(r0 + i) * C + c0 + threadIdx.x];
    __syncthreads();
    for (int i = threadIdx.y; i < 32; i += 8)
        out[(size_t)(c0 + i) * R + r0 + threadIdx.x] = __float2half(t[threadIdx.x][i]);
}

// In-place RoPE on fp16 qkv. q scaled by 0.125*log2(e) (log2-domain softmax).
__global__ void rope_h(__half* __restrict__ qkv, const float* __restrict__ rope)
{
    const float kQScale = 0.125f * 1.4426950408889634f;
    int idx = blockIdx.x * blockDim.x + threadIdx.x;  // over B*T*H*32
    int i = idx & 31;
    int h = (idx >> 5) & 15;
    int t = (idx >> 9) & (kNT - 1);
    int b = idx >> 20;

    float2 cs = ((const float2*)rope)[t * 32 + i];
    size_t base = ((size_t)(b * kNT + t)) * 3072 + h * 64 + 2 * i;

    uint32_t qv = *(uint32_t*)&qkv[base];
    __half2 qh = *(__half2*)&qv;
    float q0 = __low2float(qh), q1 = __high2float(qh);
    *(uint32_t*)&qkv[base] =
        packh2((q0 * cs.x - q1 * cs.y) * kQScale,
               (q1 * cs.x + q0 * cs.y) * kQScale);

    uint32_t kv = *(uint32_t*)&qkv[base + 1024];
    __half2 kh = *(__half2*)&kv;
    float k0 = __low2float(kh), k1 = __high2float(kh);
    *(uint32_t*)&qkv[base + 1024] =
        packh2(k0 * cs.x - k1 * cs.y, k1 * cs.x + k0 * cs.y);
}

// ---------------------------------------------------------------------------
// fp16 GEMM: C[M,N] = A[M,K] @ Bt[N,K]^T. 128x128 CTA, BK=32, 128 threads
// (4 warps 2x2), warp tile 64x64, ldmatrix.x4 loads, 3-stage cp.async ring.
// ---------------------------------------------------------------------------
constexpr int RST  = 20;                 // uints per smem row (32 fp16 + pad)
constexpr int GBUF = 2 * 128 * RST;      // uints per buffer (A+B)
constexpr int GEMM_SMEM = 3 * GBUF * 4;  // 61440 B

template <bool HOUT>
__global__ __launch_bounds__(128, 2) void gemm_f16(
    const __half* __restrict__ A, const __half* __restrict__ Bt,
    void* __restrict__ Cv, int M, int N, int K)
{
    extern __shared__ uint32_t gsh[];

    const int tid  = threadIdx.x;
    const int warp = tid >> 5, lane = tid & 31;
    const int g  = lane >> 2;
    const int i4 = lane & 3;
    const int wm = (warp >> 1) * 64;
    const int wn = (warp & 1) * 64;
    const int brow = blockIdx.y * 128;
    const int bcol = blockIdx.x * 128;
    const uint32_t sbase = sptr(gsh);

    const int a_row = lane & 15;
    const int a_col = (lane >> 4) * 16;
    const int b_row = (lane & 7) + ((lane >> 4) & 1) * 8;
    const int b_col = ((lane >> 3) & 1) * 16;

    float4 acc[4][8];
    #pragma unroll
    for (int mt = 0; mt < 4; mt++)
        #pragma unroll
        for (int nt = 0; nt < 8; nt++)
            acc[mt][nt] = make_float4(0.f, 0.f, 0.f, 0.f);

    const int NIT = K >> 5;   // BK=32

    auto stage = [&](int s, int buf) {
        uint32_t ab = sbase + buf * GBUF * 4;
        uint32_t bb = ab + 128 * RST * 4;
        const __half* Ag = A + (size_t)brow * K + (s << 5);
        const __half* Bg = Bt + (size_t)bcol * K + (s << 5);
        #pragma unroll
        for (int i = 0; i < 4; i++) {
            int id = tid + 128 * i;          // 0..511
            int r = id >> 2, ch = id & 3;    // 128 rows x 4 16B-chunks
            CP_ASYNC16(ab + r * 80 + ch * 16, Ag + (size_t)r * K + ch * 8);
            CP_ASYNC16(bb + r * 80 + ch * 16, Bg + (size_t)r * K + ch * 8);
        }
        CP_COMMIT();
    };

    stage(0, 0);
    stage(1, 1);

    #pragma unroll 1
    for (int s = 0; s < NIT; s++) {
        const int b = s % 3;
        if (s < NIT - 1) { asm volatile("cp.async.wait_group 1;"); }
        else             { asm volatile("cp.async.wait_group 0;"); }
        __syncthreads();

        if (s + 2 < NIT) stage(s + 2, (s + 2) % 3);

        const uint32_t a_s = sbase + b * GBUF * 4;
        const uint32_t b_s = a_s + 128 * RST * 4;

        #pragma unroll
        for (int kk = 0; kk < 2; kk++) {
            uint32_t af[4][4], bf[8][2];
            #pragma unroll
            for (int mt = 0; mt < 4; mt++) {
                uint32_t ad = a_s + (wm + mt * 16 + a_row) * 80
                                  + kk * 32 + a_col;
                LDSM_X4(af[mt][0], af[mt][1], af[mt][2], af[mt][3], ad);
            }
            #pragma unroll
            for (int ntp = 0; ntp < 4; ntp++) {
                uint32_t bd = b_s + (wn + ntp * 16 + b_row) * 80
                                  + kk * 32 + b_col;
                LDSM_X4(bf[2 * ntp][0], bf[2 * ntp][1],
                        bf[2 * ntp + 1][0], bf[2 * ntp + 1][1], bd);
            }
            #pragma unroll
            for (int mt = 0; mt < 4; mt++)
                #pragma unroll
                for (int nt = 0; nt < 8; nt++)
                    mma_f16(acc[mt][nt], af[mt], bf[nt]);
        }
    }

    // Epilogue
    #pragma unroll
    for (int mt = 0; mt < 4; mt++) {
        int row = brow + wm + mt * 16 + g;
        #pragma unroll
        for (int nt = 0; nt < 8; nt++) {
            int col = bcol + wn + nt * 8 + i4 * 2;
            if (HOUT) {
                __half* C = (__half*)Cv;
                *(uint32_t*)&C[(size_t)row * N + col] =
                    packh2(acc[mt][nt].x, acc[mt][nt].y);
                *(uint32_t*)&C[(size_t)(row + 8) * N + col] =
                    packh2(acc[mt][nt].z, acc[mt][nt].w);
            } else {
                float* C = (float*)Cv;
                *(float2*)&C[(size_t)row * N + col] =
                    make_float2(acc[mt][nt].x, acc[mt][nt].y);
                *(float2*)&C[(size_t)(row + 8) * N + col] =
                    make_float2(acc[mt][nt].z, acc[mt][nt].w);
            }
        }
    }
}

// ---------------------------------------------------------------------------
// Flash attention, fp16 MMA, log2-domain softmax (q pre-scaled by log2e).
// BM=128 (4 warps x m32), BN=64, HD=64, causal, 128 threads. P in registers
// via ex2.approx.f16x2; row-sum l accumulated by a ones-column MMA.
// ---------------------------------------------------------------------------
constexpr int AST = 36;   // uints per smem row (64 fp16 + pad)
constexpr int ATTN_SMEM = (128 * AST + 3 * 2 * 64 * AST) * 4;   // 73728 B

__global__ __launch_bounds__(128, 2) void attn_f16(
    const __half* __restrict__ qkv, __half* __restrict__ out)
{
    extern __shared__ uint32_t ash[];
    uint32_t* Qs   = ash;                       // [128 m][AST]
    uint32_t* Ring = Qs + 128 * AST;            // 3 x (K[64][AST] + V[64][AST])

    const int tid  = threadIdx.x;
    const int warp = tid >> 5, lane = tid & 31;
    const int g  = lane >> 2;
    const int i4 = lane & 3;
    const int qt = gridDim.x - 1 - blockIdx.x;   // big tiles first
    const int h  = blockIdx.y;
    const int b  = blockIdx.z;
    const uint32_t qbase = sptr(Qs);
    const uint32_t rbase = sptr(Ring);

    const int a_row = lane & 15;
    const int a_col = (lane >> 4) * 16;
    const int b_row = (lane & 7) + ((lane >> 4) & 1) * 8;
    const int b_col = ((lane >> 3) & 1) * 16;
    const int v_row = lane & 15;
    const int v_sel = (lane >> 4) & 1;

    const uint32_t onesb[2] = {0x3C003C00u, 0x3C003C00u};   // half2(1,1)

    const __half* qg = qkv + ((size_t)(b * kNT + qt * 128)) * 3072 + h * 64;

    // ---- Q tile via cp.async (pre-roped, pre-scaled to log2 domain) ----
    #pragma unroll
    for (int i = 0; i < 8; i++) {
        int id = tid + 128 * i;          // 0..1023
        int r = id >> 3, ch = id & 7;
        CP_ASYNC16(qbase + r * 144 + ch * 16, qg + (size_t)r * 3072 + ch * 8);
    }
    CP_COMMIT();

    const int nkt = 2 * qt + 2;
    auto stage = [&](int kt, int buf) {
        uint32_t kb = rbase + buf * 2 * 64 * AST * 4;
        uint32_t vb = kb + 64 * AST * 4;
        const __half* kg = qkv + ((size_t)(b * kNT + kt * 64)) * 3072
                               + h * 64 + 1024;
        #pragma unroll
        for (int i = 0; i < 4; i++) {
            int id = tid + 128 * i;      // 0..511
            int r = id >> 3, ch = id & 7;
            CP_ASYNC16(kb + r * 144 + ch * 16, kg + (size_t)r * 3072 + ch * 8);
            CP_ASYNC16(vb + r * 144 + ch * 16,
                       kg + 1024 + (size_t)r * 3072 + ch * 8);
        }
        CP_COMMIT();
    };

    stage(0, 0);
    stage(1, 1);

    asm volatile("cp.async.wait_group 2;");
    __syncthreads();

    uint32_t qf[2][4][4];
    #pragma unroll
    for (int mt = 0; mt < 2; mt++)
        #pragma unroll
        for (int kk = 0; kk < 4; kk++) {
            uint32_t ad = qbase + (warp * 32 + mt * 16 + a_row) * 144
                               + kk * 32 + a_col;
            LDSM_X4(qf[mt][kk][0], qf[mt][kk][1], qf[mt][kk][2], qf[mt][kk][3], ad);
        }

    float m[2][2];
    #pragma unroll
    for (int mt = 0; mt < 2; mt++) { m[mt][0] = m[mt][1] = -1e30f; }
    float4 lacc[2];
    lacc[0] = make_float4(0.f, 0.f, 0.f, 0.f);
    lacc[1] = make_float4(0.f, 0.f, 0.f, 0.f);
    float4 o[2][8];
    #pragma unroll
    for (int mt = 0; mt < 2; mt++)
        #pragma unroll
        for (int nt = 0; nt < 8; nt++)
            o[mt][nt] = make_float4(0.f, 0.f, 0.f, 0.f);

    #pragma unroll 1
    for (int kt = 0; kt < nkt; kt++) {
        if (kt < nkt - 1) { asm volatile("cp.async.wait_group 1;"); }
        else              { asm volatile("cp.async.wait_group 0;"); }
        __syncthreads();   // stage(kt) visible; compute on kt-1 done by all

        if (kt + 2 < nkt) stage(kt + 2, (kt + 2) % 3);

        const uint32_t kb = rbase + (kt % 3) * 2 * 64 * AST * 4;
        const uint32_t vb = kb + 64 * AST * 4;

        if (kt * 64 <= qt * 128 + warp * 32 + 31) {
            // ---- S = Q @ K^T (log2 domain) ----
            float4 s[2][8];
            #pragma unroll
            for (int mt = 0; mt < 2; mt++)
                #pragma unroll
                for (int nt = 0; nt < 8; nt++)
                    s[mt][nt] = make_float4(0.f, 0.f, 0.f, 0.f);

            #pragma unroll
            for (int kk = 0; kk < 4; kk++) {
                uint32_t bf[8][2];
                #pragma unroll
                for (int ntp = 0; ntp < 4; ntp++) {
                    uint32_t bd = kb + (ntp * 16 + b_row) * 144
                                     + kk * 32 + b_col;
                    LDSM_X4(bf[2 * ntp][0], bf[2 * ntp][1],
                            bf[2 * ntp + 1][0], bf[2 * ntp + 1][1], bd);
                }
                #pragma unroll
                for (int nt = 0; nt < 8; nt++) {
                    mma_f16(s[0][nt], qf[0][kk], bf[nt]);
                    mma_f16(s[1][nt], qf[1][kk], bf[nt]);
                }
            }

            // ---- Causal mask ----
            if (kt >= 2 * qt) {
                #pragma unroll
                for (int mt = 0; mt < 2; mt++) {
                    int r0 = qt * 128 + warp * 32 + mt * 16 + g;
                    #pragma unroll
                    for (int nt = 0; nt < 8; nt++) {
                        int c0 = kt * 64 + nt * 8 + i4 * 2;
                        if (c0     > r0)     s[mt][nt].x = -1e30f;
                        if (c0 + 1 > r0)     s[mt][nt].y = -1e30f;
                        if (c0     > r0 + 8) s[mt][nt].z = -1e30f;
                        if (c0 + 1 > r0 + 8) s[mt][nt].w = -1e30f;
                    }
                }
            }

            // ---- Online softmax (log2): P = 2^(s-nm) via f16x2, l via MMA ----
            uint32_t pf[2][8][2];
            #pragma unroll
            for (int mt = 0; mt < 2; mt++) {
                float mx0 = -1e30f, mx1 = -1e30f;
                #pragma unroll
                for (int nt = 0; nt < 8; nt++) {
                    mx0 = fmaxf(mx0, fmaxf(s[mt][nt].x, s[mt][nt].y));
                    mx1 = fmaxf(mx1, fmaxf(s[mt][nt].z, s[mt][nt].w));
                }
                mx0 = fmaxf(mx0, __shfl_xor_sync(0xffffffffu, mx0, 1));
                mx0 = fmaxf(mx0, __shfl_xor_sync(0xffffffffu, mx0, 2));
                mx1 = fmaxf(mx1, __shfl_xor_sync(0xffffffffu, mx1, 1));
                mx1 = fmaxf(mx1, __shfl_xor_sync(0xffffffffu, mx1, 2));
                float nm0 = fmaxf(m[mt][0], mx0), nm1 = fmaxf(m[mt][1], mx1);
                float f0 = exp2f(m[mt][0] - nm0), f1 = exp2f(m[mt][1] - nm1);
                m[mt][0] = nm0;  m[mt][1] = nm1;
                #pragma unroll
                for (int nt = 0; nt < 8; nt++) {
                    pf[mt][nt][0] = h2exp2u(
                        packh2(s[mt][nt].x - nm0, s[mt][nt].y - nm0));
                    pf[mt][nt][1] = h2exp2u(
                        packh2(s[mt][nt].z - nm1, s[mt][nt].w - nm1));
                }
                lacc[mt].x *= f0; lacc[mt].y *= f0;
                lacc[mt].z *= f1; lacc[mt].w *= f1;
                #pragma unroll
                for (int nt = 0; nt < 8; nt++) {
                    o[mt][nt].x *= f0; o[mt][nt].y *= f0;
                    o[mt][nt].z *= f1; o[mt][nt].w *= f1;
                }
            }

            // ---- O += P @ V, l += P @ ones (P in registers) ----
            #pragma unroll
            for (int kk = 0; kk < 4; kk++) {
                uint32_t af[2][4];
                #pragma unroll
                for (int mt = 0; mt < 2; mt++) {
                    af[mt][0] = pf[mt][2 * kk][0];
                    af[mt][1] = pf[mt][2 * kk][1];
                    af[mt][2] = pf[mt][2 * kk + 1][0];
                    af[mt][3] = pf[mt][2 * kk + 1][1];
                }
                uint32_t bf[8][2];
                #pragma unroll
                for (int ntp = 0; ntp < 4; ntp++) {
                    uint32_t va = vb + (kk * 16 + v_row) * 144
                                     + (2 * ntp + v_sel) * 16;
                    LDSM_X4_T(bf[2 * ntp][0], bf[2 * ntp][1],
                              bf[2 * ntp + 1][0], bf[2 * ntp + 1][1], va);
                }
                mma_f16(lacc[0], af[0], onesb);
                mma_f16(lacc[1], af[1], onesb);
                #pragma unroll
                for (int nt = 0; nt < 8; nt++) {
                    mma_f16(o[0][nt], af[0], bf[nt]);
                    mma_f16(o[1][nt], af[1], bf[nt]);
                }
            }
        }
    }

    // ---- Epilogue: fp16 output ----
    #pragma unroll
    for (int mt = 0; mt < 2; mt++) {
        float inv0 = 1.0f / lacc[mt].x, inv1 = 1.0f / lacc[mt].z;
        int r = qt * 128 + warp * 32 + mt * 16 + g;
        #pragma unroll
        for (int nt = 0; nt < 8; nt++) {
            int col = h * 64 + nt * 8 + i4 * 2;
            *(uint32_t*)&out[((size_t)(b * kNT + r)) * 1024 + col] =
                packh2(o[mt][nt].x * inv0, o[mt][nt].y * inv0);
            *(uint32_t*)&out[((size_t)(b * kNT + r + 8)) * 1024 + col] =
                packh2(o[mt][nt].z * inv1, o[mt][nt].w * inv1);
        }
    }
}

// ---------------------------------------------------------------------------
// Launch
// ---------------------------------------------------------------------------
extern "C" void kernel_launch(void* const* d_in, const int* in_sizes, int n_in,
                              void* d_out, int out_size)
{
    const float* x      = (const float*)d_in[0];
    const float* rope   = (const float*)d_in[1];
    const float* W_attn = (const float*)d_in[2];
    const float* W_proj = (const float*)d_in[3];
    float* out = (float*)d_out;

    __half* qkv;  cudaGetSymbolAddress((void**)&qkv,  g_qkv);
    __half* attn; cudaGetSymbolAddress((void**)&attn, g_attn);
    __half* xh;   cudaGetSymbolAddress((void**)&xh,   g_xh);
    __half* wat;  cudaGetSymbolAddress((void**)&wat,  g_wat);
    __half* wpt;  cudaGetSymbolAddress((void**)&wpt,  g_wpt);

    cudaFuncSetAttribute((const void*)gemm_f16<true>,
                         cudaFuncAttributeMaxDynamicSharedMemorySize, GEMM_SMEM);
    cudaFuncSetAttribute((const void*)gemm_f16<false>,
                         cudaFuncAttributeMaxDynamicSharedMemorySize, GEMM_SMEM);
    cudaFuncSetAttribute((const void*)attn_f16,
                         cudaFuncAttributeMaxDynamicSharedMemorySize, ATTN_SMEM);

    // Prepass: x -> fp16; W_attn/W_proj -> fp16 transposed [n][k]
    cvt_h<<<(kNM * kND / 4) / 256, 256>>>(x, xh);
    transpose_h<<<dim3(3 * kND / 32, kND / 32), dim3(32, 8)>>>(W_attn, wat,
                                                               kND, 3 * kND);
    transpose_h<<<dim3(kND / 32, kND / 32), dim3(32, 8)>>>(W_proj, wpt,
                                                           kND, kND);

    // 1. QKV = x @ W_attn (fp16 out)
    gemm_f16<true><<<dim3(3 * kND / 128, kNM / 128), 128, GEMM_SMEM>>>(
        xh, wat, qkv, kNM, 3 * kND, kND);

    // 2. RoPE in place (q scaled by 0.125*log2e for log2-domain softmax)
    rope_h<<<(kNB * kNT * kNH * 32) / 256, 256>>>(qkv, rope);

    // 3. Causal flash attention
    attn_f16<<<dim3(kNT / 128, kNH, kNB), 128, ATTN_SMEM>>>(qkv, attn);

    // 4. out = attn @ W_proj : fp32 out
    gemm_f16<false><<<dim3(kND / 128, kNM / 128), 128, GEMM_SMEM>>>(
        attn, wpt, out, kNM, kND, kND);
}

// round 14
// speedup vs baseline: 1.4840x; 1.0057x over previous
#include <cuda_runtime.h>
#include <cuda_fp16.h>
#include <cstdint>

// Problem constants
constexpr int kNB = 2;
constexpr int kNT = 2048;
constexpr int kND = 1024;
constexpr int kNH = 16;
constexpr int kNM = kNB * kNT;   // 4096 rows

// Scratch (allocation-free rule: device globals), all fp16
__device__ __half g_qkv[(size_t)kNM * 3 * kND];   // (4096, 3072)
__device__ __half g_attn[(size_t)kNM * kND];      // (4096, 1024)
__device__ __half g_xh[(size_t)kNM * kND];        // x -> fp16 [m][k]
__device__ __half g_wat[(size_t)3 * kND * kND];   // W_attn^T fp16 [n][k]
__device__ __half g_wpt[(size_t)kND * kND];       // W_proj^T fp16 [n][k]

// ---------------------------------------------------------------------------
// Helpers
// ---------------------------------------------------------------------------
__device__ __forceinline__ uint32_t packh2(float a, float b) {
    __half2 h = __floats2half2_rn(a, b);
    return *(uint32_t*)&h;
}

__device__ __forceinline__ uint32_t h2exp2u(uint32_t a) {
    uint32_t d;
    asm("ex2.approx.f16x2 %0, %1;" : "=r"(d) : "r"(a));
    return d;
}

__device__ __forceinline__ void mma_f16(float4& c, const uint32_t a[4],
                                        const uint32_t b[2]) {
    asm volatile(
        "mma.sync.aligned.m16n8k16.row.col.f32.f16.f16.f32 "
        "{%0,%1,%2,%3}, {%4,%5,%6,%7}, {%8,%9}, {%0,%1,%2,%3};\n"
        : "+f"(c.x), "+f"(c.y), "+f"(c.z), "+f"(c.w)
        : "r"(a[0]), "r"(a[1]), "r"(a[2]), "r"(a[3]), "r"(b[0]), "r"(b[1]));
}

#define LDSM_X4(r0, r1, r2, r3, addr) \
    asm volatile("ldmatrix.sync.aligned.m8n8.x4.shared.b16 {%0,%1,%2,%3}, [%4];" \
                 : "=r"(r0), "=r"(r1), "=r"(r2), "=r"(r3) : "r"(addr))

#define LDSM_X4_T(r0, r1, r2, r3, addr) \
    asm volatile("ldmatrix.sync.aligned.m8n8.x4.trans.shared.b16 {%0,%1,%2,%3}, [%4];" \
                 : "=r"(r0), "=r"(r1), "=r"(r2), "=r"(r3) : "r"(addr))

__device__ __forceinline__ unsigned sptr(const void* p) {
    return (unsigned)__cvta_generic_to_shared(p);
}
#define CP_ASYNC16(dst, src) \
    asm volatile("cp.async.cg.shared.global [%0], [%1], 16;" :: "r"(dst), "l"(src))
#define CP_COMMIT() asm volatile("cp.async.commit_group;")

// ---------------------------------------------------------------------------
// Prepass kernels
// ---------------------------------------------------------------------------
__global__ void cvt_h(const float* __restrict__ in, __half* __restrict__ out)
{
    int i = blockIdx.x * blockDim.x + threadIdx.x;
    float4 v = ((const float4*)in)[i];
    uint2 o;
    o.x = packh2(v.x, v.y);
    o.y = packh2(v.z, v.w);
    ((uint2*)out)[i] = o;
}

__global__ void transpose_h(const float* __restrict__ in, __half* __restrict__ out,
                            int R, int C)
{
    __shared__ float t[32][33];
    int c0 = blockIdx.x * 32, r0 = blockIdx.y * 32;
    for (int i = threadIdx.y; i < 32; i += 8)
        t[i][threadIdx.x] = in[(size_t)(r0 + i) * C + c0 + threadIdx.x];
    __syncthreads();
    for (int i = threadIdx.y; i < 32; i += 8)
        out[(size_t)(c0 + i) * R + r0 + threadIdx.x] = __float2half(t[threadIdx.x][i]);
}

// In-place RoPE on fp16 qkv. q scaled by 0.125*log2(e) (log2-domain softmax).
__global__ void rope_h(__half* __restrict__ qkv, const float* __restrict__ rope)
{
    const float kQScale = 0.125f * 1.4426950408889634f;
    int idx = blockIdx.x * blockDim.x + threadIdx.x;  // over B*T*H*32
    int i = idx & 31;
    int h = (idx >> 5) & 15;
    int t = (idx >> 9) & (kNT - 1);
    int b = idx >> 20;

    float2 cs = ((const float2*)rope)[t * 32 + i];
    size_t base = ((size_t)(b * kNT + t)) * 3072 + h * 64 + 2 * i;

    uint32_t qv = *(uint32_t*)&qkv[base];
    __half2 qh = *(__half2*)&qv;
    float q0 = __low2float(qh), q1 = __high2float(qh);
    *(uint32_t*)&qkv[base] =
        packh2((q0 * cs.x - q1 * cs.y) * kQScale,
               (q1 * cs.x + q0 * cs.y) * kQScale);

    uint32_t kv = *(uint32_t*)&qkv[base + 1024];
    __half2 kh = *(__half2*)&kv;
    float k0 = __low2float(kh), k1 = __high2float(kh);
    *(uint32_t*)&qkv[base + 1024] =
        packh2(k0 * cs.x - k1 * cs.y, k1 * cs.x + k0 * cs.y);
}

// ---------------------------------------------------------------------------
// fp16 GEMM: C[M,N] = A[M,K] @ Bt[N,K]^T. 128x128 CTA, BK=32, 128 threads
// (4 warps 2x2), warp tile 64x64. 4-stage cp.async ring with register-level
// fragment double buffering: next-iter kk=0 fragments prefetched after the
// barrier; kk=1 fragments loaded under kk=0's MMAs. Tensor pipe never waits
// on LDSM in steady state.
// ---------------------------------------------------------------------------
constexpr int RST  = 20;                 // uints per smem row (32 fp16 + pad)
constexpr int GBUF = 2 * 128 * RST;      // uints per buffer (A+B)
constexpr int GEMM_SMEM = 4 * GBUF * 4;  // 81920 B

template <bool HOUT>
__global__ __launch_bounds__(128, 2) void gemm_f16(
    const __half* __restrict__ A, const __half* __restrict__ Bt,
    void* __restrict__ Cv, int M, int N, int K)
{
    extern __shared__ uint32_t gsh[];

    const int tid  = threadIdx.x;
    const int warp = tid >> 5, lane = tid & 31;
    const int g  = lane >> 2;
    const int i4 = lane & 3;
    const int wm = (warp >> 1) * 64;
    const int wn = (warp & 1) * 64;
    const int brow = blockIdx.y * 128;
    const int bcol = blockIdx.x * 128;
    const uint32_t sbase = sptr(gsh);

    const int a_row = lane & 15;
    const int a_col = (lane >> 4) * 16;
    const int b_row = (lane & 7) + ((lane >> 4) & 1) * 8;
    const int b_col = ((lane >> 3) & 1) * 16;

    float4 acc[4][8];
    #pragma unroll
    for (int mt = 0; mt < 4; mt++)
        #pragma unroll
        for (int nt = 0; nt < 8; nt++)
            acc[mt][nt] = make_float4(0.f, 0.f, 0.f, 0.f);

    const int NIT = K >> 5;   // BK=32

    auto stage = [&](int s) {
        int buf = s & 3;
        uint32_t ab = sbase + buf * GBUF * 4;
        uint32_t bb = ab + 128 * RST * 4;
        const __half* Ag = A + (size_t)brow * K + (s << 5);
        const __half* Bg = Bt + (size_t)bcol * K + (s << 5);
        #pragma unroll
        for (int i = 0; i < 4; i++) {
            int id = tid + 128 * i;          // 0..511
            int r = id >> 2, ch = id & 3;    // 128 rows x 4 16B-chunks
            CP_ASYNC16(ab + r * 80 + ch * 16, Ag + (size_t)r * K + ch * 8);
            CP_ASYNC16(bb + r * 80 + ch * 16, Bg + (size_t)r * K + ch * 8);
        }
    };

    // Fragment double buffers: [kk-slot][...]
    uint32_t af[2][4][4], bf[2][8][2];

    auto ldfrags = [&](int s, int kk, int fb) {
        uint32_t base = sbase + (s & 3) * GBUF * 4;
        uint32_t b_s = base + 128 * RST * 4;
        #pragma unroll
        for (int mt = 0; mt < 4; mt++) {
            uint32_t ad = base + (wm + mt * 16 + a_row) * 80 + kk * 32 + a_col;
            LDSM_X4(af[fb][mt][0], af[fb][mt][1], af[fb][mt][2], af[fb][mt][3], ad);
        }
        #pragma unroll
        for (int ntp = 0; ntp < 4; ntp++) {
            uint32_t bd = b_s + (wn + ntp * 16 + b_row) * 80 + kk * 32 + b_col;
            LDSM_X4(bf[fb][2 * ntp][0], bf[fb][2 * ntp][1],
                    bf[fb][2 * ntp + 1][0], bf[fb][2 * ntp + 1][1], bd);
        }
    };

    // Prologue: 3 stages in flight, first fragments resident.
    stage(0); CP_COMMIT();
    stage(1); CP_COMMIT();
    stage(2); CP_COMMIT();
    asm volatile("cp.async.wait_group 2;");   // group 0 done
    __syncthreads();
    ldfrags(0, 0, 0);

    #pragma unroll 1
    for (int s = 0; s < NIT; s++) {
        // Stage s+3 (empty commit keeps group accounting uniform).
        if (s + 3 < NIT) stage(s + 3);
        CP_COMMIT();

        // kk=1 fragments load under kk=0's MMAs.
        ldfrags(s, 1, 1);

        #pragma unroll
        for (int mt = 0; mt < 4; mt++)
            #pragma unroll
            for (int nt = 0; nt < 8; nt++)
                mma_f16(acc[mt][nt], af[0][mt], bf[0][nt]);

        #pragma unroll
        for (int mt = 0; mt < 4; mt++)
            #pragma unroll
            for (int nt = 0; nt < 8; nt++)
                mma_f16(acc[mt][nt], af[1][mt], bf[1][nt]);

        // Ensure group s+1 landed (pending <= {s+2, s+3}), make visible, and
        // prefetch next iteration's kk=0 fragments.
        asm volatile("cp.async.wait_group 2;");
        __syncthreads();
        if (s + 1 < NIT) ldfrags(s + 1, 0, 0);
    }

    // Epilogue
    #pragma unroll
    for (int mt = 0; mt < 4; mt++) {
        int row = brow + wm + mt * 16 + g;
        #pragma unroll
        for (int nt = 0; nt < 8; nt++) {
            int col = bcol + wn + nt * 8 + i4 * 2;
            if (HOUT) {
                __half* C = (__half*)Cv;
                *(uint32_t*)&C[(size_t)row * N + col] =
                    packh2(acc[mt][nt].x, acc[mt][nt].y);
                *(uint32_t*)&C[(size_t)(row + 8) * N + col] =
                    packh2(acc[mt][nt].z, acc[mt][nt].w);
            } else {
                float* C = (float*)Cv;
                *(float2*)&C[(size_t)row * N + col] =
                    make_float2(acc[mt][nt].x, acc[mt][nt].y);
                *(float2*)&C[(size_t)(row + 8) * N + col] =
                    make_float2(acc[mt][nt].z, acc[mt][nt].w);
            }
        }
    }
}

// ---------------------------------------------------------------------------
// Flash attention, fp16 MMA, log2-domain softmax (q pre-scaled by log2e).
// BM=128 (4 warps x m32), BN=64, HD=64, causal, 128 threads. P in registers
// via ex2.approx.f16x2; row-sum l accumulated by a ones-column MMA.
// (Unchanged from R13.)
// ---------------------------------------------------------------------------
constexpr int AST = 36;   // uints per smem row (64 fp16 + pad)
constexpr int ATTN_SMEM = (128 * AST + 3 * 2 * 64 * AST) * 4;   // 73728 B

__global__ __launch_bounds__(128, 2) void attn_f16(
    const __half* __restrict__ qkv, __half* __restrict__ out)
{
    extern __shared__ uint32_t ash[];
    uint32_t* Qs   = ash;                       // [128 m][AST]
    uint32_t* Ring = Qs + 128 * AST;            // 3 x (K[64][AST] + V[64][AST])

    const int tid  = threadIdx.x;
    const int warp = tid >> 5, lane = tid & 31;
    const int g  = lane >> 2;
    const int i4 = lane & 3;
    const int qt = gridDim.x - 1 - blockIdx.x;   // big tiles first
    const int h  = blockIdx.y;
    const int b  = blockIdx.z;
    const uint32_t qbase = sptr(Qs);
    const uint32_t rbase = sptr(Ring);

    const int a_row = lane & 15;
    const int a_col = (lane >> 4) * 16;
    const int b_row = (lane & 7) + ((lane >> 4) & 1) * 8;
    const int b_col = ((lane >> 3) & 1) * 16;
    const int v_row = lane & 15;
    const int v_sel = (lane >> 4) & 1;

    const uint32_t onesb[2] = {0x3C003C00u, 0x3C003C00u};   // half2(1,1)

    const __half* qg = qkv + ((size_t)(b * kNT + qt * 128)) * 3072 + h * 64;

    #pragma unroll
    for (int i = 0; i < 8; i++) {
        int id = tid + 128 * i;          // 0..1023
        int r = id >> 3, ch = id & 7;
        CP_ASYNC16(qbase + r * 144 + ch * 16, qg + (size_t)r * 3072 + ch * 8);
    }
    CP_COMMIT();

    const int nkt = 2 * qt + 2;
    auto stage = [&](int kt, int buf) {
        uint32_t kb = rbase + buf * 2 * 64 * AST * 4;
        uint32_t vb = kb + 64 * AST * 4;
        const __half* kg = qkv + ((size_t)(b * kNT + kt * 64)) * 3072
                               + h * 64 + 1024;
        #pragma unroll
        for (int i = 0; i < 4; i++) {
            int id = tid + 128 * i;      // 0..511
            int r = id >> 3, ch = id & 7;
            CP_ASYNC16(kb + r * 144 + ch * 16, kg + (size_t)r * 3072 + ch * 8);
            CP_ASYNC16(vb + r * 144 + ch * 16,
                       kg + 1024 + (size_t)r * 3072 + ch * 8);
        }
        CP_COMMIT();
    };

    stage(0, 0);
    stage(1, 1);

    asm volatile("cp.async.wait_group 2;");
    __syncthreads();

    uint32_t qf[2][4][4];
    #pragma unroll
    for (int mt = 0; mt < 2; mt++)
        #pragma unroll
        for (int kk = 0; kk < 4; kk++) {
            uint32_t ad = qbase + (warp * 32 + mt * 16 + a_row) * 144
                               + kk * 32 + a_col;
            LDSM_X4(qf[mt][kk][0], qf[mt][kk][1], qf[mt][kk][2], qf[mt][kk][3], ad);
        }

    float m[2][2];
    #pragma unroll
    for (int mt = 0; mt < 2; mt++) { m[mt][0] = m[mt][1] = -1e30f; }
    float4 lacc[2];
    lacc[0] = make_float4(0.f, 0.f, 0.f, 0.f);
    lacc[1] = make_float4(0.f, 0.f, 0.f, 0.f);
    float4 o[2][8];
    #pragma unroll
    for (int mt = 0; mt < 2; mt++)
        #pragma unroll
        for (int nt = 0; nt < 8; nt++)
            o[mt][nt] = make_float4(0.f, 0.f, 0.f, 0.f);

    #pragma unroll 1
    for (int kt = 0; kt < nkt; kt++) {
        if (kt < nkt - 1) { asm volatile("cp.async.wait_group 1;"); }
        else              { asm volatile("cp.async.wait_group 0;"); }
        __syncthreads();

        if (kt + 2 < nkt) stage(kt + 2, (kt + 2) % 3);

        const uint32_t kb = rbase + (kt % 3) * 2 * 64 * AST * 4;
        const uint32_t vb = kb + 64 * AST * 4;

        if (kt * 64 <= qt * 128 + warp * 32 + 31) {
            float4 s[2][8];
            #pragma unroll
            for (int mt = 0; mt < 2; mt++)
                #pragma unroll
                for (int nt = 0; nt < 8; nt++)
                    s[mt][nt] = make_float4(0.f, 0.f, 0.f, 0.f);

            #pragma unroll
            for (int kk = 0; kk < 4; kk++) {
                uint32_t bf[8][2];
                #pragma unroll
                for (int ntp = 0; ntp < 4; ntp++) {
                    uint32_t bd = kb + (ntp * 16 + b_row) * 144
                                     + kk * 32 + b_col;
                    LDSM_X4(bf[2 * ntp][0], bf[2 * ntp][1],
                            bf[2 * ntp + 1][0], bf[2 * ntp + 1][1], bd);
                }
                #pragma unroll
                for (int nt = 0; nt < 8; nt++) {
                    mma_f16(s[0][nt], qf[0][kk], bf[nt]);
                    mma_f16(s[1][nt], qf[1][kk], bf[nt]);
                }
            }

            if (kt >= 2 * qt) {
                #pragma unroll
                for (int mt = 0; mt < 2; mt++) {
                    int r0 = qt * 128 + warp * 32 + mt * 16 + g;
                    #pragma unroll
                    for (int nt = 0; nt < 8; nt++) {
                        int c0 = kt * 64 + nt * 8 + i4 * 2;
                        if (c0     > r0)     s[mt][nt].x = -1e30f;
                        if (c0 + 1 > r0)     s[mt][nt].y = -1e30f;
                        if (c0     > r0 + 8) s[mt][nt].z = -1e30f;
                        if (c0 + 1 > r0 + 8) s[mt][nt].w = -1e30f;
                    }
                }
            }

            uint32_t pf[2][8][2];
            #pragma unroll
            for (int mt = 0; mt < 2; mt++) {
                float mx0 = -1e30f, mx1 = -1e30f;
                #pragma unroll
                for (int nt = 0; nt < 8; nt++) {
                    mx0 = fmaxf(mx0, fmaxf(s[mt][nt].x, s[mt][nt].y));
                    mx1 = fmaxf(mx1, fmaxf(s[mt][nt].z, s[mt][nt].w));
                }
                mx0 = fmaxf(mx0, __shfl_xor_sync(0xffffffffu, mx0, 1));
                mx0 = fmaxf(mx0, __shfl_xor_sync(0xffffffffu, mx0, 2));
                mx1 = fmaxf(mx1, __shfl_xor_sync(0xffffffffu, mx1, 1));
                mx1 = fmaxf(mx1, __shfl_xor_sync(0xffffffffu, mx1, 2));
                float nm0 = fmaxf(m[mt][0], mx0), nm1 = fmaxf(m[mt][1], mx1);
                float f0 = exp2f(m[mt][0] - nm0), f1 = exp2f(m[mt][1] - nm1);
                m[mt][0] = nm0;  m[mt][1] = nm1;
                #pragma unroll
                for (int nt = 0; nt < 8; nt++) {
                    pf[mt][nt][0] = h2exp2u(
                        packh2(s[mt][nt].x - nm0, s[mt][nt].y - nm0));
                    pf[mt][nt][1] = h2exp2u(
                        packh2(s[mt][nt].z - nm1, s[mt][nt].w - nm1));
                }
                lacc[mt].x *= f0; lacc[mt].y *= f0;
                lacc[mt].z *= f1; lacc[mt].w *= f1;
                #pragma unroll
                for (int nt = 0; nt < 8; nt++) {
                    o[mt][nt].x *= f0; o[mt][nt].y *= f0;
                    o[mt][nt].z *= f1; o[mt][nt].w *= f1;
                }
            }

            #pragma unroll
            for (int kk = 0; kk < 4; kk++) {
                uint32_t af[2][4];
                #pragma unroll
                for (int mt = 0; mt < 2; mt++) {
                    af[mt][0] = pf[mt][2 * kk][0];
                    af[mt][1] = pf[mt][2 * kk][1];
                    af[mt][2] = pf[mt][2 * kk + 1][0];
                    af[mt][3] = pf[mt][2 * kk + 1][1];
                }
                uint32_t bf[8][2];
                #pragma unroll
                for (int ntp = 0; ntp < 4; ntp++) {
                    uint32_t va = vb + (kk * 16 + v_row) * 144
                                     + (2 * ntp + v_sel) * 16;
                    LDSM_X4_T(bf[2 * ntp][0], bf[2 * ntp][1],
                              bf[2 * ntp + 1][0], bf[2 * ntp + 1][1], va);
                }
                mma_f16(lacc[0], af[0], onesb);
                mma_f16(lacc[1], af[1], onesb);
                #pragma unroll
                for (int nt = 0; nt < 8; nt++) {
                    mma_f16(o[0][nt], af[0], bf[nt]);
                    mma_f16(o[1][nt], af[1], bf[nt]);
                }
            }
        }
    }

    #pragma unroll
    for (int mt = 0; mt < 2; mt++) {
        float inv0 = 1.0f / lacc[mt].x, inv1 = 1.0f / lacc[mt].z;
        int r = qt * 128 + warp * 32 + mt * 16 + g;
        #pragma unroll
        for (int nt = 0; nt < 8; nt++) {
            int col = h * 64 + nt * 8 + i4 * 2;
            *(uint32_t*)&out[((size_t)(b * kNT + r)) * 1024 + col] =
                packh2(o[mt][nt].x * inv0, o[mt][nt].y * inv0);
            *(uint32_t*)&out[((size_t)(b * kNT + r + 8)) * 1024 + col] =
                packh2(o[mt][nt].z * inv1, o[mt][nt].w * inv1);
        }
    }
}

// ---------------------------------------------------------------------------
// Launch
// ---------------------------------------------------------------------------
extern "C" void kernel_launch(void* const* d_in, const int* in_sizes, int n_in,
                              void* d_out, int out_size)
{
    const float* x      = (const float*)d_in[0];
    const float* rope   = (const float*)d_in[1];
    const float* W_attn = (const float*)d_in[2];
    const float* W_proj = (const float*)d_in[3];
    float* out = (float*)d_out;

    __half* qkv;  cudaGetSymbolAddress((void**)&qkv,  g_qkv);
    __half* attn; cudaGetSymbolAddress((void**)&attn, g_attn);
    __half* xh;   cudaGetSymbolAddress((void**)&xh,   g_xh);
    __half* wat;  cudaGetSymbolAddress((void**)&wat,  g_wat);
    __half* wpt;  cudaGetSymbolAddress((void**)&wpt,  g_wpt);

    cudaFuncSetAttribute((const void*)gemm_f16<true>,
                         cudaFuncAttributeMaxDynamicSharedMemorySize, GEMM_SMEM);
    cudaFuncSetAttribute((const void*)gemm_f16<false>,
                         cudaFuncAttributeMaxDynamicSharedMemorySize, GEMM_SMEM);
    cudaFuncSetAttribute((const void*)attn_f16,
                         cudaFuncAttributeMaxDynamicSharedMemorySize, ATTN_SMEM);

    // Prepass: x -> fp16; W_attn/W_proj -> fp16 transposed [n][k]
    cvt_h<<<(kNM * kND / 4) / 256, 256>>>(x, xh);
    transpose_h<<<dim3(3 * kND / 32, kND / 32), dim3(32, 8)>>>(W_attn, wat,
                                                               kND, 3 * kND);
    transpose_h<<<dim3(kND / 32, kND / 32), dim3(32, 8)>>>(W_proj, wpt,
                                                           kND, kND);

    // 1. QKV = x @ W_attn (fp16 out)
    gemm_f16<true><<<dim3(3 * kND / 128, kNM / 128), 128, GEMM_SMEM>>>(
        xh, wat, qkv, kNM, 3 * kND, kND);

    // 2. RoPE in place (q scaled by 0.125*log2e for log2-domain softmax)
    rope_h<<<(kNB * kNT * kNH * 32) / 256, 256>>>(qkv, rope);

    // 3. Causal flash attention
    attn_f16<<<dim3(kNT / 128, kNH, kNB), 128, ATTN_SMEM>>>(qkv, attn);

    // 4. out = attn @ W_proj : fp32 out
    gemm_f16<false><<<dim3(kND / 128, kNM / 128), 128, GEMM_SMEM>>>(
        attn, wpt, out, kNM, kND, kND);
}